// round 9
// baseline (speedup 1.0000x reference)
#include <cuda_runtime.h>
#include <math.h>

#define BB 4
#define NN 1024
#define KNNK 16
#define N3 3072
#define NCOL 12288
#define CATC 352
#define EPSF 1e-12f

// ---- static scratch ----
__device__ __align__(16) float g_cat[BB * CATC * 3 * NN];     // [b][c][d][n]
__device__ __align__(16) float g_Out[(size_t)NCOL * 512];     // [cid][og]
__device__ __align__(16) float g_Wall[512 * 128];             // [og][c]
__device__ __align__(16) float g_Dc[NCOL];
__device__ __align__(16) float g_ycc[BB * 128 * 3 * NN];
__device__ __align__(16) float g_y[BB * 128 * 3];
__device__ int g_idx[BB * NN * KNNK];

// ---- KNN (PROTECTED rounding structure — do not change) ----
__global__ void knn_k(const float* __restrict__ x) {
    __shared__ float ssq[NN];
    __shared__ float sd[NN];
    __shared__ float rv[8];
    __shared__ int   ri[8];
    int bn = blockIdx.x;
    int b = bn >> 10, n = bn & (NN - 1);
    int tid = threadIdx.x;
    const float* xb = x + (size_t)b * N3;
    for (int m = tid; m < NN; m += 256) {
        float qx = xb[m], qy = xb[NN + m], qz = xb[2*NN + m];
        ssq[m] = __fadd_rn(__fadd_rn(__fmul_rn(qx, qx), __fmul_rn(qy, qy)),
                           __fmul_rn(qz, qz));
    }
    __syncthreads();
    float px = xb[n], py = xb[NN + n], pz = xb[2*NN + n];
    float sqn = ssq[n];
    for (int m = tid; m < NN; m += 256) {
        float qx = xb[m], qy = xb[NN + m], qz = xb[2*NN + m];
        float dot = __fmaf_rn(pz, qz, __fmaf_rn(py, qy, __fmul_rn(px, qx)));
        sd[m] = __fsub_rn(__fadd_rn(sqn, ssq[m]), __fmul_rn(2.0f, dot));
    }
    __syncthreads();
    for (int k = 0; k < KNNK; k++) {
        float bv = INFINITY; int bi = 0x7fffffff;
        for (int m = tid; m < NN; m += 256) {
            float v = sd[m];
            if (v < bv || (v == bv && m < bi)) { bv = v; bi = m; }
        }
        for (int off = 16; off > 0; off >>= 1) {
            float ov = __shfl_down_sync(0xffffffffu, bv, off);
            int   oi = __shfl_down_sync(0xffffffffu, bi, off);
            if (ov < bv || (ov == bv && oi < bi)) { bv = ov; bi = oi; }
        }
        if ((tid & 31) == 0) { rv[tid >> 5] = bv; ri[tid >> 5] = bi; }
        __syncthreads();
        if (tid == 0) {
            float fv = rv[0]; int fi = ri[0];
            for (int w = 1; w < 8; w++)
                if (rv[w] < fv || (rv[w] == fv && ri[w] < fi)) { fv = rv[w]; fi = ri[w]; }
            g_idx[bn * KNNK + k] = fi;
            sd[fi] = INFINITY;
        }
        __syncthreads();
    }
}

// ---- pack layer weights: Wall = [W1; W2-W1; Wd@W1; Wd@(W2-W1)] ----
__global__ void wpack_k(const float* __restrict__ W, const float* __restrict__ Wd,
                        int Cin, int Cout) {
    int o = blockIdx.x;
    int c = threadIdx.x;
    if (c >= Cin) return;
    float w1 = W[o*2*Cin + c], w2 = W[o*2*Cin + Cin + c];
    g_Wall[(size_t)o * Cin + c] = w1;
    g_Wall[(size_t)(Cout + o) * Cin + c] = w2 - w1;
    float s1 = 0.f, s2 = 0.f;
    for (int m = 0; m < Cout; m++) {
        float wd = Wd[o*Cout + m];
        s1 += wd * W[m*2*Cin + c];
        s2 += wd * W[m*2*Cin + Cin + c];
    }
    g_Wall[(size_t)(2*Cout + o) * Cin + c] = s1;
    g_Wall[(size_t)(3*Cout + o) * Cin + c] = s2 - s1;
}

// ---- smem-tiled GEMM: 128 cols x 128 outs per block, scalar FFMA ----
__global__ __launch_bounds__(256, 2)
void gemmT_k(const float* __restrict__ Wext, int wsel,
             const float* __restrict__ xin, int finoff,
             int Cin, size_t bstride, int OutTot) {
    __shared__ float fs[32][128];
    __shared__ float ws[128][32];
    const float* Wall = wsel ? g_Wall : Wext;
    int cid0 = blockIdx.x * 128;
    int o0 = blockIdx.y * 128;
    int b = cid0 / N3;
    int dn0 = cid0 - b * N3;
    const float* fin = (xin ? xin : (g_cat + finoff)) + (size_t)b * bstride + dn0;
    int tid = threadIdx.x;
    int colg = tid & 15;   // 16 groups x 8 cols
    int rowg = tid >> 4;   // 16 groups x 8 rows
    float acc[8][8];
#pragma unroll
    for (int i = 0; i < 8; i++)
#pragma unroll
        for (int j = 0; j < 8; j++) acc[i][j] = 0.f;

    for (int kc = 0; kc < Cin; kc += 32) {
        int kmax = min(32, Cin - kc);
        __syncthreads();
        for (int idx = tid; idx < kmax * 32; idx += 256) {
            int r = idx >> 5, cq = idx & 31;
            *(float4*)&fs[r][cq*4] =
                *(const float4*)&fin[(size_t)(kc + r) * N3 + cq*4];
        }
        if (kmax == 32) {
            for (int idx = tid; idx < 128 * 8; idx += 256) {
                int r = idx >> 3, kq = idx & 7;
                *(float4*)&ws[r][kq*4] =
                    *(const float4*)&Wall[(size_t)(o0 + r) * Cin + kc + kq*4];
            }
        } else {
            for (int idx = tid; idx < 128 * kmax; idx += 256) {
                int r = idx / kmax, k = idx - r * kmax;
                ws[r][k] = Wall[(size_t)(o0 + r) * Cin + kc + k];
            }
        }
        __syncthreads();
#pragma unroll 4
        for (int k = 0; k < kmax; k++) {
            float fr[8];
            *(float4*)&fr[0] = *(const float4*)&fs[k][colg*8];
            *(float4*)&fr[4] = *(const float4*)&fs[k][colg*8 + 4];
#pragma unroll
            for (int i = 0; i < 8; i++) {
                float w = ws[rowg*8 + i][k];
#pragma unroll
                for (int j = 0; j < 8; j++) acc[i][j] += w * fr[j];
            }
        }
    }
    // store: cid = cid0 + colg*8 + j, o = o0 + rowg*8 + i
#pragma unroll
    for (int j = 0; j < 8; j++) {
        int cid = cid0 + colg*8 + j;
        float* op = g_Out + (size_t)cid * OutTot + o0 + rowg*8;
        float4 v0 = make_float4(acc[0][j], acc[1][j], acc[2][j], acc[3][j]);
        float4 v1 = make_float4(acc[4][j], acc[5][j], acc[6][j], acc[7][j]);
        *(float4*)op = v0; *(float4*)(op + 4) = v1;
    }
}

// ---- edge: gather + vec_act + mean over K ----
__global__ void edge_k(int Cout, int OutTot, int coff, int P) {
    int tid = threadIdx.x;
    int p = tid / Cout;
    int c = tid - p * Cout;
    int bn = blockIdx.x * P + p;
    int b = bn >> 10, n = bn & (NN - 1);
    const int* ip = g_idx + bn * KNNK;
    size_t sN = (size_t)NN * OutTot;
    size_t pn = (size_t)(b * N3 + n) * OutTot;
    float bm0 = g_Out[pn + Cout + c],   bm1 = g_Out[pn + sN + Cout + c],   bm2 = g_Out[pn + 2*sN + Cout + c];
    float bd0 = g_Out[pn + 3*Cout + c], bd1 = g_Out[pn + sN + 3*Cout + c], bd2 = g_Out[pn + 2*sN + 3*Cout + c];
    float a0 = 0.f, a1 = 0.f, a2 = 0.f;
#pragma unroll 2
    for (int k = 0; k < KNNK; k++) {
        int j = ip[k];
        size_t pj = (size_t)(b * N3 + j) * OutTot;
        float y0 = g_Out[pj + c]        + bm0;
        float y1 = g_Out[pj + sN + c]   + bm1;
        float y2 = g_Out[pj + 2*sN + c] + bm2;
        float d0 = g_Out[pj + 2*Cout + c]        + bd0;
        float d1 = g_Out[pj + sN + 2*Cout + c]   + bd1;
        float d2 = g_Out[pj + 2*sN + 2*Cout + c] + bd2;
        float dm = fmaxf(sqrtf(d0*d0 + d1*d1 + d2*d2), EPSF);
        float k0 = d0/dm, k1 = d1/dm, k2 = d2/dm;
        float dot = y0*k0 + y1*k1 + y2*k2;
        float coef = (dot < 0.f) ? (-0.8f * dot) : 0.f;
        a0 += y0 + coef*k0; a1 += y1 + coef*k1; a2 += y2 + coef*k2;
    }
    const float s = 1.0f / 16.0f;
    size_t ob = ((size_t)(b * CATC + coff + c) * 3) * NN + n;
    g_cat[ob] = a0 * s; g_cat[ob + NN] = a1 * s; g_cat[ob + 2*NN] = a2 * s;
}

// ---- g_Dc: warp-per-cid coalesced dot ----
__global__ void dc_k(const float* __restrict__ ccD) {
    int w = threadIdx.x >> 5, lane = threadIdx.x & 31;
    int cid = blockIdx.x * 8 + w;
    const float* u = g_Out + (size_t)cid * 128;
    float s = 0.f;
#pragma unroll
    for (int i = 0; i < 4; i++) s += ccD[i*32 + lane] * u[i*32 + lane];
    for (int off = 16; off > 0; off >>= 1)
        s += __shfl_down_sync(0xffffffffu, s, off);
    if (lane == 0) g_Dc[cid] = s;
}

// ---- cc vec_act with shared 1-channel direction ----
__global__ void ccact_k() {
    int bn = blockIdx.x;
    int b = bn >> 10, n = bn & (NN - 1);
    int c = threadIdx.x;
    int bn0 = b * N3 + n;
    float d0 = g_Dc[bn0], d1 = g_Dc[bn0 + NN], d2 = g_Dc[bn0 + 2*NN];
    float dm = fmaxf(sqrtf(d0*d0 + d1*d1 + d2*d2), EPSF);
    float k0 = d0/dm, k1 = d1/dm, k2 = d2/dm;
    size_t sN = (size_t)NN * 128;
    size_t p = (size_t)bn0 * 128 + c;
    float u0 = g_Out[p], u1 = g_Out[p + sN], u2 = g_Out[p + 2*sN];
    float dot = u0*k0 + u1*k1 + u2*k2;
    float coef = (dot < 0.f) ? (-0.8f * dot) : 0.f;
    size_t ob = ((size_t)(b * 128 + c) * 3) * NN + n;
    g_ycc[ob] = u0 + coef*k0; g_ycc[ob + NN] = u1 + coef*k1; g_ycc[ob + 2*NN] = u2 + coef*k2;
}

// ---- mean over N ----
__global__ void reduce_k() {
    __shared__ float s[256];
    const float* p = g_ycc + (size_t)blockIdx.x * NN;
    int t = threadIdx.x;
    s[t] = p[t] + p[t + 256] + p[t + 512] + p[t + 768];
    __syncthreads();
    for (int off = 128; off > 0; off >>= 1) {
        if (t < off) s[t] += s[t + off];
        __syncthreads();
    }
    if (t == 0) g_y[blockIdx.x] = s[0] * (1.0f / NN);
}

// ---- head helpers: 384 threads, (c, d) parallel ----
__device__ void gemm3p(float (*dst)[3], const float* __restrict__ W,
                       const float (*src)[3], int Cout, int Cin, int c, int d) {
    if (c < Cout) {
        float s = 0.f;
        for (int m = 0; m < Cin; m++) s += W[c*Cin + m] * src[m][d];
        dst[c][d] = s;
    }
    __syncthreads();
}
__device__ void act3p(float (*dst)[3], const float (*x)[3],
                      const float* __restrict__ Wd, int C, int c, int d,
                      float (*tmp)[3]) {
    if (c < C) {
        float s = 0.f;
        for (int m = 0; m < C; m++) s += Wd[c*C + m] * x[m][d];
        tmp[c][d] = s;
    }
    __syncthreads();
    if (c < C) {
        float d0 = tmp[c][0], d1 = tmp[c][1], d2 = tmp[c][2];
        float dm = fmaxf(sqrtf(d0*d0 + d1*d1 + d2*d2), EPSF);
        float k0 = d0/dm, k1 = d1/dm, k2 = d2/dm;
        float dot = x[c][0]*k0 + x[c][1]*k1 + x[c][2]*k2;
        float coef = (dot < 0.f) ? (-0.8f * dot) : 0.f;
        float kk = (d == 0) ? k0 : ((d == 1) ? k1 : k2);
        dst[c][d] = x[c][d] + coef*kk;
    }
    __syncthreads();
}

__global__ void head_k(const float* __restrict__ fcO,
                       const float* __restrict__ rbDin, const float* __restrict__ rbW0,
                       const float* __restrict__ rbDh,  const float* __restrict__ rbW1,
                       const float* __restrict__ rbWs,
                       const float* __restrict__ m0W, const float* __restrict__ m0D,
                       const float* __restrict__ m1W, const float* __restrict__ m1D,
                       const float* __restrict__ l0W, const float* __restrict__ l0D,
                       const float* __restrict__ l1W, const float* __restrict__ l1D,
                       const float* __restrict__ fimW, const float* __restrict__ filW,
                       float* __restrict__ out) {
    int b = blockIdx.x;
    int tid = threadIdx.x;
    int d = tid >> 7;         // 0..2
    int c = tid & 127;
    __shared__ float sy[128][3], syn[128][3], t0[128][3], t1[128][3], t2[128][3], tdir[128][3];
    __shared__ float snorm[128];
    __shared__ float sr[384];
    __shared__ float sR[9];
    __shared__ float sS[1];

    sy[c][d] = g_y[(b*128 + c)*3 + d];
    __syncthreads();
    if (d == 0) {
        float y0 = sy[c][0], y1 = sy[c][1], y2 = sy[c][2];
        snorm[c] = sqrtf(y0*y0 + y1*y1 + y2*y2);
    }
    __syncthreads();

    // scale = mean(nc + EPS) * 640
    if (d == 0) sr[c] = snorm[c] + EPSF;
    __syncthreads();
    for (int off = 64; off > 0; off >>= 1) {
        if (d == 0 && c < off) sr[c] += sr[c + off];
        __syncthreads();
    }
    if (tid == 0) out[1060 + b] = sr[0] * (1.0f / 128.0f) * 640.0f;
    __syncthreads();

    // S = sum nc^2 ; cevn
    if (d == 0) sr[c] = snorm[c] * snorm[c];
    __syncthreads();
    for (int off = 64; off > 0; off >>= 1) {
        if (d == 0 && c < off) sr[c] += sr[c + off];
        __syncthreads();
    }
    if (tid == 0) sS[0] = fmaxf(sqrtf(sr[0]), EPSF);
    __syncthreads();
    {
        float nn = snorm[c] / sS[0];
        float inv = fmaxf(snorm[c], EPSF);
        syn[c][d] = sy[c][d] / inv * nn;
    }
    __syncthreads();

    // R[d][o] = sum_c fcO[o][c]*syn[c][d]
    for (int o = 0; o < 3; o++) {
        sr[tid] = fcO[o*128 + c] * syn[c][d];
        __syncthreads();
        for (int off = 64; off > 0; off >>= 1) {
            if (c < off) sr[d*128 + c] += sr[d*128 + c + off];
            __syncthreads();
        }
        if (c == 0) sR[d*3 + o] = sr[d*128];
        __syncthreads();
    }

    // polar (det-scaled Newton); so3_out = transpose(Q)
    if (tid == 0) {
        float X[9], Cf[9];
        float fn = 0.f;
        for (int i = 0; i < 9; i++) { X[i] = sR[i]; fn += X[i]*X[i]; }
        fn = sqrtf(fn); if (fn < 1e-20f) fn = 1e-20f;
        for (int i = 0; i < 9; i++) X[i] /= fn;
        for (int it = 0; it < 25; it++) {
            Cf[0] =  (X[4]*X[8] - X[5]*X[7]);
            Cf[1] = -(X[3]*X[8] - X[5]*X[6]);
            Cf[2] =  (X[3]*X[7] - X[4]*X[6]);
            Cf[3] = -(X[1]*X[8] - X[2]*X[7]);
            Cf[4] =  (X[0]*X[8] - X[2]*X[6]);
            Cf[5] = -(X[0]*X[7] - X[1]*X[6]);
            Cf[6] =  (X[1]*X[5] - X[2]*X[4]);
            Cf[7] = -(X[0]*X[5] - X[2]*X[3]);
            Cf[8] =  (X[0]*X[4] - X[1]*X[3]);
            float det = X[0]*Cf[0] + X[1]*Cf[1] + X[2]*Cf[2];
            float ad = fabsf(det);
            if (ad < 1e-30f) break;
            float z = 1.0f / cbrtf(ad);
            float invd = 1.0f / det;
            for (int i = 0; i < 9; i++)
                X[i] = 0.5f * (z * X[i] + (Cf[i] * invd) / z);
        }
        for (int i = 0; i < 3; i++)
            for (int j = 0; j < 3; j++)
                out[1024 + b*9 + i*3 + j] = X[j*3 + i];
    }

    // residual block: center
    act3p(t0, sy, rbDin, 128, c, d, tdir);
    gemm3p(t1, rbW0, t0, 64, 128, c, d);
    act3p(t2, t1, rbDh, 64, c, d, tdir);
    if (tid < 3) {
        float dx = 0.f;
        for (int m = 0; m < 64; m++) dx += rbW1[m] * t2[m][tid];
        float wsv = 0.f;
        for (int m = 0; m < 128; m++) wsv += rbWs[m] * sy[m][tid];
        out[1064 + b*3 + tid] = (wsv + dx) * 640.0f;
    }
    __syncthreads();

    // mean branch
    gemm3p(t0, m0W, syn, 128, 128, c, d);
    act3p(t1, t0, m0D, 128, c, d, tdir);
    gemm3p(t0, m1W, t1, 128, 128, c, d);
    act3p(t2, t0, m1D, 128, c, d, tdir);
    gemm3p(t0, fimW, t2, 128, 128, c, d);
    if (d == 0)
        out[b*128 + c] = t2[c][0]*t0[c][0] + t2[c][1]*t0[c][1] + t2[c][2]*t0[c][2];
    __syncthreads();

    // logvar branch
    gemm3p(t0, l0W, syn, 128, 128, c, d);
    act3p(t1, t0, l0D, 128, c, d, tdir);
    gemm3p(t0, l1W, t1, 128, 128, c, d);
    act3p(t2, t0, l1D, 128, c, d, tdir);
    gemm3p(t0, filW, t2, 128, 128, c, d);
    if (d == 0)
        out[512 + b*128 + c] = t2[c][0]*t0[c][0] + t2[c][1]*t0[c][1] + t2[c][2]*t0[c][2];
}

// ---- host-side layer driver ----
static void run_layer(const float* W, const float* Wd, int Cin, int Cout,
                      const float* xin, int finoff, size_t bstride, int coff) {
    int OutTot = 4 * Cout;
    wpack_k<<<Cout, Cin>>>(W, Wd, Cin, Cout);
    dim3 g(96, OutTot / 128);
    gemmT_k<<<g, 256>>>(nullptr, 1, xin, finoff, Cin, bstride, OutTot);
    int P = 128 / Cout;
    edge_k<<<BB * NN / P, 128>>>(Cout, OutTot, coff, P);
}

extern "C" void kernel_launch(void* const* d_in, const int* in_sizes, int n_in,
                              void* d_out, int out_size) {
    const float* x    = (const float*)d_in[0];
    const float* c1W  = (const float*)d_in[2];
    const float* c1D  = (const float*)d_in[3];
    const float* c2W  = (const float*)d_in[4];
    const float* c2D  = (const float*)d_in[5];
    const float* c3W  = (const float*)d_in[6];
    const float* c3D  = (const float*)d_in[7];
    const float* c4W  = (const float*)d_in[8];
    const float* c4D  = (const float*)d_in[9];
    const float* ccW  = (const float*)d_in[10];
    const float* ccD  = (const float*)d_in[11];
    const float* fcO  = (const float*)d_in[12];
    const float* m0W  = (const float*)d_in[13];
    const float* m0D  = (const float*)d_in[14];
    const float* m1W  = (const float*)d_in[15];
    const float* m1D  = (const float*)d_in[16];
    const float* l0W  = (const float*)d_in[17];
    const float* l0D  = (const float*)d_in[18];
    const float* l1W  = (const float*)d_in[19];
    const float* l1D  = (const float*)d_in[20];
    const float* fimW = (const float*)d_in[21];
    const float* filW = (const float*)d_in[22];
    const float* rbDin= (const float*)d_in[23];
    const float* rbW0 = (const float*)d_in[24];
    const float* rbDh = (const float*)d_in[25];
    const float* rbW1 = (const float*)d_in[26];
    const float* rbWs = (const float*)d_in[27];
    float* out = (float*)d_out;

    knn_k<<<BB * NN, 256>>>(x);

    size_t catbs = (size_t)CATC * N3;
    run_layer(c1W, c1D, 1,   32,  x,       0,        (size_t)N3, 0);
    run_layer(c2W, c2D, 32,  64,  nullptr, 0,        catbs,      32);
    run_layer(c3W, c3D, 64,  128, nullptr, 32 * N3,  catbs,      96);
    run_layer(c4W, c4D, 128, 128, nullptr, 96 * N3,  catbs,      224);

    // cc layer: U = ccW @ cat  (OutTot=128, weights direct)
    {
        dim3 g(96, 1);
        gemmT_k<<<g, 256>>>(ccW, 0, nullptr, 0, CATC, catbs, 128);
    }
    dc_k<<<NCOL / 8, 256>>>(ccD);
    ccact_k<<<BB * NN, 128>>>();
    reduce_k<<<BB * 128 * 3, 256>>>();

    head_k<<<BB, 384>>>(fcO, rbDin, rbW0, rbDh, rbW1, rbWs,
                        m0W, m0D, m1W, m1D, l0W, l0D, l1W, l1D,
                        fimW, filW, out);
}

// round 10
// speedup vs baseline: 1.2350x; 1.2350x over previous
#include <cuda_runtime.h>
#include <math.h>

#define BB 4
#define NN 1024
#define KNNK 16
#define N3 3072
#define NCOL 12288
#define CATC 352
#define WPSLOT 32768
#define EPSF 1e-12f

// ---- static scratch ----
__device__ __align__(16) float g_cat[BB * CATC * 3 * NN];  // [b][c][d][n]
__device__ __align__(16) float g_A [NCOL * 128];           // [cid][o], cid=b*3N+d*N+n
__device__ __align__(16) float g_Bm[NCOL * 128];
__device__ __align__(16) float g_Ad[NCOL * 128];
__device__ __align__(16) float g_Bd[NCOL * 128];
__device__ __align__(16) float g_U [NCOL * 128];
__device__ __align__(16) float g_Wp[4 * WPSLOT];
__device__ __align__(16) float g_ycc[BB * 128 * 3 * NN];
__device__ __align__(16) float g_y[BB * 128 * 3];
__device__ int g_idx[BB * NN * KNNK];

// ---- KNN (PROTECTED rounding structure — do not change) ----
__global__ void knn_k(const float* __restrict__ x) {
    __shared__ float ssq[NN];
    __shared__ float sd[NN];
    __shared__ float rv[8];
    __shared__ int   ri[8];
    int bn = blockIdx.x;
    int b = bn >> 10, n = bn & (NN - 1);
    int tid = threadIdx.x;
    const float* xb = x + (size_t)b * N3;
    for (int m = tid; m < NN; m += 256) {
        float qx = xb[m], qy = xb[NN + m], qz = xb[2*NN + m];
        ssq[m] = __fadd_rn(__fadd_rn(__fmul_rn(qx, qx), __fmul_rn(qy, qy)),
                           __fmul_rn(qz, qz));
    }
    __syncthreads();
    float px = xb[n], py = xb[NN + n], pz = xb[2*NN + n];
    float sqn = ssq[n];
    for (int m = tid; m < NN; m += 256) {
        float qx = xb[m], qy = xb[NN + m], qz = xb[2*NN + m];
        float dot = __fmaf_rn(pz, qz, __fmaf_rn(py, qy, __fmul_rn(px, qx)));
        sd[m] = __fsub_rn(__fadd_rn(sqn, ssq[m]), __fmul_rn(2.0f, dot));
    }
    __syncthreads();
    for (int k = 0; k < KNNK; k++) {
        float bv = INFINITY; int bi = 0x7fffffff;
        for (int m = tid; m < NN; m += 256) {
            float v = sd[m];
            if (v < bv || (v == bv && m < bi)) { bv = v; bi = m; }
        }
        for (int off = 16; off > 0; off >>= 1) {
            float ov = __shfl_down_sync(0xffffffffu, bv, off);
            int   oi = __shfl_down_sync(0xffffffffu, bi, off);
            if (ov < bv || (ov == bv && oi < bi)) { bv = ov; bi = oi; }
        }
        if ((tid & 31) == 0) { rv[tid >> 5] = bv; ri[tid >> 5] = bi; }
        __syncthreads();
        if (tid == 0) {
            float fv = rv[0]; int fi = ri[0];
            for (int w = 1; w < 8; w++)
                if (rv[w] < fv || (rv[w] == fv && ri[w] < fi)) { fv = rv[w]; fi = ri[w]; }
            g_idx[bn * KNNK + k] = fi;
            sd[fi] = INFINITY;
        }
        __syncthreads();
    }
}

// ---- all 4 layers' Wp = Wd @ W in ONE launch ----
__global__ void wcomb_all_k(const float* __restrict__ W1, const float* __restrict__ D1,
                            const float* __restrict__ W2, const float* __restrict__ D2,
                            const float* __restrict__ W3, const float* __restrict__ D3,
                            const float* __restrict__ W4, const float* __restrict__ D4) {
    int bid = blockIdx.x;
    const float *W, *Wd; int Cin, Cout, o, slot;
    if (bid < 32)       { W = W1; Wd = D1; Cin = 1;   Cout = 32;  o = bid;       slot = 0; }
    else if (bid < 96)  { W = W2; Wd = D2; Cin = 32;  Cout = 64;  o = bid - 32;  slot = 1; }
    else if (bid < 224) { W = W3; Wd = D3; Cin = 64;  Cout = 128; o = bid - 96;  slot = 2; }
    else                { W = W4; Wd = D4; Cin = 128; Cout = 128; o = bid - 224; slot = 3; }
    int wcols = 2 * Cin;
    int j = threadIdx.x;
    if (j >= wcols) return;
    float s = 0.f;
    for (int m = 0; m < Cout; m++) s += Wd[o * Cout + m] * W[m * wcols + j];
    g_Wp[slot * WPSLOT + o * wcols + j] = s;
}

// ---- skinny GEMM over 12288 columns (R6-proven form) ----
__device__ __forceinline__ float* out_sel(int s) {
    switch (s) {
        case 0: return g_A;
        case 1: return g_Bm;
        case 2: return g_Ad;
        case 3: return g_Bd;
        default: return g_U;
    }
}
__global__ void gemm_k(const float* __restrict__ Wparam, int wsel, int wpoff,
                       int ldw, int mode,
                       const float* __restrict__ xin, int finoff,
                       int Cin, size_t bstride, int outsel, int Cout) {
    extern __shared__ float ws[];
    const float* W = wsel ? (g_Wp + wpoff) : Wparam;
    const int R = 8;
    int o0 = blockIdx.y * R;
    for (int t = threadIdx.x; t < R * Cin; t += blockDim.x) {
        int i = t / Cin, c = t - i * Cin;
        float w = W[(o0 + i) * ldw + c];
        if (mode) w = W[(o0 + i) * ldw + Cin + c] - w;
        ws[t] = w;
    }
    __syncthreads();
    const float* FIN = xin ? xin : (g_cat + finoff);
    float* OUT = out_sel(outsel);
    int cid = (blockIdx.x * blockDim.x + threadIdx.x) * 4;
    int b = cid / N3;
    int dn = cid - b * N3;
    const float* fin = FIN + (size_t)b * bstride + dn;
    float acc[8][4];
#pragma unroll
    for (int i = 0; i < 8; i++) { acc[i][0]=0.f; acc[i][1]=0.f; acc[i][2]=0.f; acc[i][3]=0.f; }
    for (int c = 0; c < Cin; c++) {
        float4 f = *reinterpret_cast<const float4*>(fin + (size_t)c * N3);
#pragma unroll
        for (int i = 0; i < 8; i++) {
            float w = ws[i * Cin + c];
            acc[i][0] += w * f.x; acc[i][1] += w * f.y;
            acc[i][2] += w * f.z; acc[i][3] += w * f.w;
        }
    }
#pragma unroll
    for (int j = 0; j < 4; j++) {
        float* op = OUT + (size_t)(cid + j) * Cout + o0;
#pragma unroll
        for (int i = 0; i < 8; i++) op[i] = acc[i][j];
    }
}

// ---- edge: gather + vec_act + mean over K (R6-proven form) ----
__global__ void edge_k(int Cout, int coff) {
    int bn = blockIdx.x;
    int b = bn >> 10, n = bn & (NN - 1);
    int c = threadIdx.x;
    const int* ip = g_idx + bn * KNNK;
    int bn0 = b * N3 + n;
    size_t sN = (size_t)NN * Cout;
    size_t pn = (size_t)bn0 * Cout + c;
    float bm0 = g_Bm[pn], bm1 = g_Bm[pn + sN], bm2 = g_Bm[pn + 2*sN];
    float bd0 = g_Bd[pn], bd1 = g_Bd[pn + sN], bd2 = g_Bd[pn + 2*sN];
    float a0 = 0.f, a1 = 0.f, a2 = 0.f;
    for (int k = 0; k < KNNK; k++) {
        int j = ip[k];
        size_t pj = (size_t)(b * N3 + j) * Cout + c;
        float y0 = g_A[pj]        + bm0;
        float y1 = g_A[pj + sN]   + bm1;
        float y2 = g_A[pj + 2*sN] + bm2;
        float d0 = g_Ad[pj]        + bd0;
        float d1 = g_Ad[pj + sN]   + bd1;
        float d2 = g_Ad[pj + 2*sN] + bd2;
        float dm = fmaxf(sqrtf(d0*d0 + d1*d1 + d2*d2), EPSF);
        float k0 = d0/dm, k1 = d1/dm, k2 = d2/dm;
        float dot = y0*k0 + y1*k1 + y2*k2;
        float coef = (dot < 0.f) ? (-0.8f * dot) : 0.f;
        a0 += y0 + coef*k0; a1 += y1 + coef*k1; a2 += y2 + coef*k2;
    }
    const float s = 1.0f / 16.0f;
    size_t ob = ((size_t)(b * CATC + coff + c) * 3) * NN + n;
    g_cat[ob] = a0 * s; g_cat[ob + NN] = a1 * s; g_cat[ob + 2*NN] = a2 * s;
}

// ---- fused cc direction-dot + vec_act: one block per (b,n) ----
__global__ void ccfused_k(const float* __restrict__ ccD) {
    __shared__ float sk[3];
    int bn = blockIdx.x;
    int b = bn >> 10, n = bn & (NN - 1);
    int tid = threadIdx.x;
    int w = tid >> 5, lane = tid & 31;
    if (w < 3) {
        int cid = b * N3 + w * NN + n;
        const float* u = g_U + (size_t)cid * 128;
        float s = 0.f;
#pragma unroll
        for (int i = 0; i < 4; i++) s += ccD[i*32 + lane] * u[i*32 + lane];
        for (int off = 16; off > 0; off >>= 1)
            s += __shfl_down_sync(0xffffffffu, s, off);
        if (lane == 0) sk[w] = s;
    }
    __syncthreads();
    float d0 = sk[0], d1 = sk[1], d2 = sk[2];
    float dm = fmaxf(sqrtf(d0*d0 + d1*d1 + d2*d2), EPSF);
    float k0 = d0/dm, k1 = d1/dm, k2 = d2/dm;
    int bn0 = b * N3 + n;
    size_t sN = (size_t)NN * 128;
    size_t p = (size_t)bn0 * 128 + tid;
    float u0 = g_U[p], u1 = g_U[p + sN], u2 = g_U[p + 2*sN];
    float dot = u0*k0 + u1*k1 + u2*k2;
    float coef = (dot < 0.f) ? (-0.8f * dot) : 0.f;
    size_t ob = ((size_t)(b * 128 + tid) * 3) * NN + n;
    g_ycc[ob] = u0 + coef*k0; g_ycc[ob + NN] = u1 + coef*k1; g_ycc[ob + 2*NN] = u2 + coef*k2;
}

// ---- mean over N ----
__global__ void reduce_k() {
    __shared__ float s[256];
    const float* p = g_ycc + (size_t)blockIdx.x * NN;
    int t = threadIdx.x;
    s[t] = p[t] + p[t + 256] + p[t + 512] + p[t + 768];
    __syncthreads();
    for (int off = 128; off > 0; off >>= 1) {
        if (t < off) s[t] += s[t + off];
        __syncthreads();
    }
    if (t == 0) g_y[blockIdx.x] = s[0] * (1.0f / NN);
}

// ---- head helpers (R6-proven form) ----
__device__ __forceinline__ float bsum128(float v, float* s) {
    int t = threadIdx.x;
    s[t] = v; __syncthreads();
    for (int off = 64; off > 0; off >>= 1) {
        if (t < off) s[t] += s[t + off];
        __syncthreads();
    }
    float r = s[0]; __syncthreads();
    return r;
}
__device__ __forceinline__ void gemm3(float (*dst)[3], const float* W,
                                      const float (*src)[3], int Cout, int Cin, int c) {
    if (c < Cout) {
        float a0 = 0.f, a1 = 0.f, a2 = 0.f;
        for (int m = 0; m < Cin; m++) {
            float w = W[c * Cin + m];
            a0 += w * src[m][0]; a1 += w * src[m][1]; a2 += w * src[m][2];
        }
        dst[c][0] = a0; dst[c][1] = a1; dst[c][2] = a2;
    }
}
__device__ __forceinline__ void act_sq(float (*dst)[3], const float (*x)[3],
                                       const float* Wd, int C, int c) {
    if (c < C) {
        float d0 = 0.f, d1 = 0.f, d2 = 0.f;
        for (int m = 0; m < C; m++) {
            float w = Wd[c * C + m];
            d0 += w * x[m][0]; d1 += w * x[m][1]; d2 += w * x[m][2];
        }
        float dm = fmaxf(sqrtf(d0*d0 + d1*d1 + d2*d2), EPSF);
        float k0 = d0/dm, k1 = d1/dm, k2 = d2/dm;
        float dot = x[c][0]*k0 + x[c][1]*k1 + x[c][2]*k2;
        float coef = (dot < 0.f) ? (-0.8f * dot) : 0.f;
        dst[c][0] = x[c][0] + coef*k0;
        dst[c][1] = x[c][1] + coef*k1;
        dst[c][2] = x[c][2] + coef*k2;
    }
}

__global__ void head_k(const float* __restrict__ fcO,
                       const float* __restrict__ rbDin, const float* __restrict__ rbW0,
                       const float* __restrict__ rbDh,  const float* __restrict__ rbW1,
                       const float* __restrict__ rbWs,
                       const float* __restrict__ m0W, const float* __restrict__ m0D,
                       const float* __restrict__ m1W, const float* __restrict__ m1D,
                       const float* __restrict__ l0W, const float* __restrict__ l0D,
                       const float* __restrict__ l1W, const float* __restrict__ l1D,
                       const float* __restrict__ fimW, const float* __restrict__ filW,
                       float* __restrict__ out) {
    int b = blockIdx.x, c = threadIdx.x;
    __shared__ float sy[128][3], syn[128][3], t0[128][3], t1[128][3], t2[128][3];
    __shared__ float sred[128];
    __shared__ float sR[9];

    float y0 = g_y[(b*128 + c)*3 + 0];
    float y1 = g_y[(b*128 + c)*3 + 1];
    float y2 = g_y[(b*128 + c)*3 + 2];
    sy[c][0] = y0; sy[c][1] = y1; sy[c][2] = y2;
    float nc = sqrtf(y0*y0 + y1*y1 + y2*y2);
    __syncthreads();

    // scale
    float ss = bsum128(nc + EPSF, sred);
    if (c == 0) out[1060 + b] = ss * (1.0f / 128.0f) * 640.0f;

    // cevn(y)
    float S = bsum128(nc * nc, sred);
    float nn = nc / fmaxf(sqrtf(S), EPSF);
    float invn = fmaxf(nc, EPSF);
    syn[c][0] = y0/invn*nn; syn[c][1] = y1/invn*nn; syn[c][2] = y2/invn*nn;
    __syncthreads();

    // R[d][o] = sum_c fcO[o][c]*syn[c][d]
    for (int o = 0; o < 3; o++) {
        float wo = fcO[o * 128 + c];
        for (int d = 0; d < 3; d++) {
            float r = bsum128(wo * syn[c][d], sred);
            if (c == 0) sR[d*3 + o] = r;
        }
    }
    __syncthreads();

    // polar (det-scaled Newton); so3_out = transpose(Q)
    if (c == 0) {
        float X[9], Cf[9];
        float fn = 0.f;
        for (int i = 0; i < 9; i++) { X[i] = sR[i]; fn += X[i]*X[i]; }
        fn = sqrtf(fn); if (fn < 1e-20f) fn = 1e-20f;
        for (int i = 0; i < 9; i++) X[i] /= fn;
        for (int it = 0; it < 25; it++) {
            Cf[0] =  (X[4]*X[8] - X[5]*X[7]);
            Cf[1] = -(X[3]*X[8] - X[5]*X[6]);
            Cf[2] =  (X[3]*X[7] - X[4]*X[6]);
            Cf[3] = -(X[1]*X[8] - X[2]*X[7]);
            Cf[4] =  (X[0]*X[8] - X[2]*X[6]);
            Cf[5] = -(X[0]*X[7] - X[1]*X[6]);
            Cf[6] =  (X[1]*X[5] - X[2]*X[4]);
            Cf[7] = -(X[0]*X[5] - X[2]*X[3]);
            Cf[8] =  (X[0]*X[4] - X[1]*X[3]);
            float det = X[0]*Cf[0] + X[1]*Cf[1] + X[2]*Cf[2];
            float ad = fabsf(det);
            if (ad < 1e-30f) break;
            float z = 1.0f / cbrtf(ad);
            float invd = 1.0f / det;
            for (int i = 0; i < 9; i++)
                X[i] = 0.5f * (z * X[i] + (Cf[i] * invd) / z);
        }
        for (int i = 0; i < 3; i++)
            for (int j = 0; j < 3; j++)
                out[1024 + b*9 + i*3 + j] = X[j*3 + i];
    }

    // residual block: center
    act_sq(t0, sy, rbDin, 128, c);
    __syncthreads();
    gemm3(t1, rbW0, t0, 64, 128, c);
    __syncthreads();
    act_sq(t2, t1, rbDh, 64, c);
    __syncthreads();
    if (c < 3) {
        float dx = 0.f;
        for (int m = 0; m < 64; m++) dx += rbW1[m] * t2[m][c];
        float wsv = 0.f;
        for (int m = 0; m < 128; m++) wsv += rbWs[m] * sy[m][c];
        out[1064 + b*3 + c] = (wsv + dx) * 640.0f;
    }
    __syncthreads();

    // mean branch
    gemm3(t0, m0W, syn, 128, 128, c); __syncthreads();
    act_sq(t1, t0, m0D, 128, c);      __syncthreads();
    gemm3(t0, m1W, t1, 128, 128, c);  __syncthreads();
    act_sq(t2, t0, m1D, 128, c);      __syncthreads();
    gemm3(t0, fimW, t2, 128, 128, c); __syncthreads();
    out[b*128 + c] = t2[c][0]*t0[c][0] + t2[c][1]*t0[c][1] + t2[c][2]*t0[c][2];
    __syncthreads();

    // logvar branch
    gemm3(t0, l0W, syn, 128, 128, c); __syncthreads();
    act_sq(t1, t0, l0D, 128, c);      __syncthreads();
    gemm3(t0, l1W, t1, 128, 128, c);  __syncthreads();
    act_sq(t2, t0, l1D, 128, c);      __syncthreads();
    gemm3(t0, filW, t2, 128, 128, c); __syncthreads();
    out[512 + b*128 + c] = t2[c][0]*t0[c][0] + t2[c][1]*t0[c][1] + t2[c][2]*t0[c][2];
}

// ---- host-side layer driver ----
static void run_layer(const float* W, int layer, int Cin, int Cout,
                      const float* xin, int finoff, size_t bstride, int coff) {
    int wcols = 2 * Cin;
    int wpoff = layer * WPSLOT;
    dim3 g(24, Cout / 8);
    size_t sm = (size_t)8 * Cin * sizeof(float);
    gemm_k<<<g, 128, sm>>>(W, 0, 0,     wcols, 0, xin, finoff, Cin, bstride, 0, Cout);
    gemm_k<<<g, 128, sm>>>(W, 0, 0,     wcols, 1, xin, finoff, Cin, bstride, 1, Cout);
    gemm_k<<<g, 128, sm>>>(W, 1, wpoff, wcols, 0, xin, finoff, Cin, bstride, 2, Cout);
    gemm_k<<<g, 128, sm>>>(W, 1, wpoff, wcols, 1, xin, finoff, Cin, bstride, 3, Cout);
    edge_k<<<BB * NN, Cout>>>(Cout, coff);
}

extern "C" void kernel_launch(void* const* d_in, const int* in_sizes, int n_in,
                              void* d_out, int out_size) {
    const float* x    = (const float*)d_in[0];
    const float* c1W  = (const float*)d_in[2];
    const float* c1D  = (const float*)d_in[3];
    const float* c2W  = (const float*)d_in[4];
    const float* c2D  = (const float*)d_in[5];
    const float* c3W  = (const float*)d_in[6];
    const float* c3D  = (const float*)d_in[7];
    const float* c4W  = (const float*)d_in[8];
    const float* c4D  = (const float*)d_in[9];
    const float* ccW  = (const float*)d_in[10];
    const float* ccD  = (const float*)d_in[11];
    const float* fcO  = (const float*)d_in[12];
    const float* m0W  = (const float*)d_in[13];
    const float* m0D  = (const float*)d_in[14];
    const float* m1W  = (const float*)d_in[15];
    const float* m1D  = (const float*)d_in[16];
    const float* l0W  = (const float*)d_in[17];
    const float* l0D  = (const float*)d_in[18];
    const float* l1W  = (const float*)d_in[19];
    const float* l1D  = (const float*)d_in[20];
    const float* fimW = (const float*)d_in[21];
    const float* filW = (const float*)d_in[22];
    const float* rbDin= (const float*)d_in[23];
    const float* rbW0 = (const float*)d_in[24];
    const float* rbDh = (const float*)d_in[25];
    const float* rbW1 = (const float*)d_in[26];
    const float* rbWs = (const float*)d_in[27];
    float* out = (float*)d_out;

    knn_k<<<BB * NN, 256>>>(x);
    wcomb_all_k<<<352, 256>>>(c1W, c1D, c2W, c2D, c3W, c3D, c4W, c4D);

    size_t catbs = (size_t)CATC * N3;
    run_layer(c1W, 0, 1,   32,  x,       0,        (size_t)N3, 0);
    run_layer(c2W, 1, 32,  64,  nullptr, 0,        catbs,      32);
    run_layer(c3W, 2, 64,  128, nullptr, 32 * N3,  catbs,      96);
    run_layer(c4W, 3, 128, 128, nullptr, 96 * N3,  catbs,      224);

    // cc layer
    {
        dim3 g(24, 16);
        size_t sm = (size_t)8 * CATC * sizeof(float);
        gemm_k<<<g, 128, sm>>>(ccW, 0, 0, CATC, 0, nullptr, 0, CATC, catbs, 4, 128);
    }
    ccfused_k<<<BB * NN, 128>>>(ccD);
    reduce_k<<<BB * 128 * 3, 256>>>();

    head_k<<<BB, 128>>>(fcO, rbDin, rbW0, rbDh, rbW1, rbWs,
                        m0W, m0D, m1W, m1D, l0W, l0D, l1W, l1D,
                        fimW, filW, out);
}

// round 11
// speedup vs baseline: 1.3091x; 1.0600x over previous
#include <cuda_runtime.h>
#include <math.h>

#define BB 4
#define NN 1024
#define KNNK 16
#define N3 3072
#define NCOL 12288
#define CATC 352
#define WPSLOT 32768
#define EPSF 1e-12f

// ---- static scratch ----
__device__ __align__(16) float g_cat[BB * CATC * 3 * NN];  // [b][c][d][n]
__device__ __align__(16) float g_A [NCOL * 128];           // [cid][o], cid=b*3N+d*N+n
__device__ __align__(16) float g_Bm[NCOL * 128];
__device__ __align__(16) float g_Ad[NCOL * 128];
__device__ __align__(16) float g_Bd[NCOL * 128];
__device__ __align__(16) float g_U [NCOL * 128];
__device__ __align__(16) float g_Wp[4 * WPSLOT];
__device__ __align__(16) float g_ycc[BB * 128 * 3 * NN];
__device__ __align__(16) float g_y[BB * 128 * 3];
__device__ int g_idx[BB * NN * KNNK];

// ---- KNN (PROTECTED rounding structure — do not change) ----
__global__ void knn_k(const float* __restrict__ x) {
    __shared__ float ssq[NN];
    __shared__ float sd[NN];
    __shared__ float rv[8];
    __shared__ int   ri[8];
    int bn = blockIdx.x;
    int b = bn >> 10, n = bn & (NN - 1);
    int tid = threadIdx.x;
    const float* xb = x + (size_t)b * N3;
    for (int m = tid; m < NN; m += 256) {
        float qx = xb[m], qy = xb[NN + m], qz = xb[2*NN + m];
        ssq[m] = __fadd_rn(__fadd_rn(__fmul_rn(qx, qx), __fmul_rn(qy, qy)),
                           __fmul_rn(qz, qz));
    }
    __syncthreads();
    float px = xb[n], py = xb[NN + n], pz = xb[2*NN + n];
    float sqn = ssq[n];
    for (int m = tid; m < NN; m += 256) {
        float qx = xb[m], qy = xb[NN + m], qz = xb[2*NN + m];
        float dot = __fmaf_rn(pz, qz, __fmaf_rn(py, qy, __fmul_rn(px, qx)));
        sd[m] = __fsub_rn(__fadd_rn(sqn, ssq[m]), __fmul_rn(2.0f, dot));
    }
    __syncthreads();
    for (int k = 0; k < KNNK; k++) {
        float bv = INFINITY; int bi = 0x7fffffff;
        for (int m = tid; m < NN; m += 256) {
            float v = sd[m];
            if (v < bv || (v == bv && m < bi)) { bv = v; bi = m; }
        }
        for (int off = 16; off > 0; off >>= 1) {
            float ov = __shfl_down_sync(0xffffffffu, bv, off);
            int   oi = __shfl_down_sync(0xffffffffu, bi, off);
            if (ov < bv || (ov == bv && oi < bi)) { bv = ov; bi = oi; }
        }
        if ((tid & 31) == 0) { rv[tid >> 5] = bv; ri[tid >> 5] = bi; }
        __syncthreads();
        if (tid == 0) {
            float fv = rv[0]; int fi = ri[0];
            for (int w = 1; w < 8; w++)
                if (rv[w] < fv || (rv[w] == fv && ri[w] < fi)) { fv = rv[w]; fi = ri[w]; }
            g_idx[bn * KNNK + k] = fi;
            sd[fi] = INFINITY;
        }
        __syncthreads();
    }
}

// ---- all 4 layers' Wp = Wd @ W in ONE launch ----
__global__ void wcomb_all_k(const float* __restrict__ W1, const float* __restrict__ D1,
                            const float* __restrict__ W2, const float* __restrict__ D2,
                            const float* __restrict__ W3, const float* __restrict__ D3,
                            const float* __restrict__ W4, const float* __restrict__ D4) {
    int bid = blockIdx.x;
    const float *W, *Wd; int Cin, Cout, o, slot;
    if (bid < 32)       { W = W1; Wd = D1; Cin = 1;   Cout = 32;  o = bid;       slot = 0; }
    else if (bid < 96)  { W = W2; Wd = D2; Cin = 32;  Cout = 64;  o = bid - 32;  slot = 1; }
    else if (bid < 224) { W = W3; Wd = D3; Cin = 64;  Cout = 128; o = bid - 96;  slot = 2; }
    else                { W = W4; Wd = D4; Cin = 128; Cout = 128; o = bid - 224; slot = 3; }
    int wcols = 2 * Cin;
    int j = threadIdx.x;
    if (j >= wcols) return;
    float s = 0.f;
    for (int m = 0; m < Cout; m++) s += Wd[o * Cout + m] * W[m * wcols + j];
    g_Wp[slot * WPSLOT + o * wcols + j] = s;
}

// ---- output selector: 0 A (W,m0), 1 Bm (W,m1), 2 Ad (Wp,m0), 3 Bd (Wp,m1), 4 U ----
__device__ __forceinline__ float* out_sel(int s) {
    switch (s) {
        case 0: return g_A;
        case 1: return g_Bm;
        case 2: return g_Ad;
        case 3: return g_Bd;
        default: return g_U;
    }
}

// ---- fused 4-way skinny GEMM: one launch per layer ----
__global__ void gemm4_k(const float* __restrict__ Wparam, int wpoff, int ldw,
                        const float* __restrict__ xin, int finoff,
                        int Cin, size_t bstride, int Cout) {
    extern __shared__ float ws[];
    const int R = 8;
    int groups = Cout >> 3;
    int which = blockIdx.y / groups;          // 0..3
    int o0 = (blockIdx.y - which * groups) * R;
    int mode = which & 1;
    const float* W = (which & 2) ? (g_Wp + wpoff) : Wparam;
    float* OUT = out_sel(which);
    for (int t = threadIdx.x; t < R * Cin; t += blockDim.x) {
        int i = t / Cin, c = t - i * Cin;
        float w = W[(o0 + i) * ldw + c];
        if (mode) w = W[(o0 + i) * ldw + Cin + c] - w;
        ws[t] = w;
    }
    __syncthreads();
    const float* FIN = xin ? xin : (g_cat + finoff);
    int cid = (blockIdx.x * blockDim.x + threadIdx.x) * 4;
    int b = cid / N3;
    int dn = cid - b * N3;
    const float* fin = FIN + (size_t)b * bstride + dn;
    float acc[8][4];
#pragma unroll
    for (int i = 0; i < 8; i++) { acc[i][0]=0.f; acc[i][1]=0.f; acc[i][2]=0.f; acc[i][3]=0.f; }
    for (int c = 0; c < Cin; c++) {
        float4 f = *reinterpret_cast<const float4*>(fin + (size_t)c * N3);
#pragma unroll
        for (int i = 0; i < 8; i++) {
            float w = ws[i * Cin + c];
            acc[i][0] += w * f.x; acc[i][1] += w * f.y;
            acc[i][2] += w * f.z; acc[i][3] += w * f.w;
        }
    }
#pragma unroll
    for (int j = 0; j < 4; j++) {
        float* op = OUT + (size_t)(cid + j) * Cout + o0;
#pragma unroll
        for (int i = 0; i < 8; i++) op[i] = acc[i][j];
    }
}

// ---- cc skinny GEMM (single output set) ----
__global__ void gemm_k(const float* __restrict__ Wparam,
                       int ldw, int Cin, size_t bstride, int Cout) {
    extern __shared__ float ws[];
    const int R = 8;
    int o0 = blockIdx.y * R;
    for (int t = threadIdx.x; t < R * Cin; t += blockDim.x) {
        int i = t / Cin, c = t - i * Cin;
        ws[t] = Wparam[(o0 + i) * ldw + c];
    }
    __syncthreads();
    int cid = (blockIdx.x * blockDim.x + threadIdx.x) * 4;
    int b = cid / N3;
    int dn = cid - b * N3;
    const float* fin = g_cat + (size_t)b * bstride + dn;
    float acc[8][4];
#pragma unroll
    for (int i = 0; i < 8; i++) { acc[i][0]=0.f; acc[i][1]=0.f; acc[i][2]=0.f; acc[i][3]=0.f; }
    for (int c = 0; c < Cin; c++) {
        float4 f = *reinterpret_cast<const float4*>(fin + (size_t)c * N3);
#pragma unroll
        for (int i = 0; i < 8; i++) {
            float w = ws[i * Cin + c];
            acc[i][0] += w * f.x; acc[i][1] += w * f.y;
            acc[i][2] += w * f.z; acc[i][3] += w * f.w;
        }
    }
#pragma unroll
    for (int j = 0; j < 4; j++) {
        float* op = g_U + (size_t)(cid + j) * Cout + o0;
#pragma unroll
        for (int i = 0; i < 8; i++) op[i] = acc[i][j];
    }
}

// ---- edge: gather + vec_act + mean over K (P points per block) ----
__global__ void edge_k(int Cout, int coff, int P) {
    int tid = threadIdx.x;
    int p = tid / Cout;
    int c = tid - p * Cout;
    int bn = blockIdx.x * P + p;
    int b = bn >> 10, n = bn & (NN - 1);
    const int* ip = g_idx + bn * KNNK;
    int bn0 = b * N3 + n;
    size_t sN = (size_t)NN * Cout;
    size_t pn = (size_t)bn0 * Cout + c;
    float bm0 = g_Bm[pn], bm1 = g_Bm[pn + sN], bm2 = g_Bm[pn + 2*sN];
    float bd0 = g_Bd[pn], bd1 = g_Bd[pn + sN], bd2 = g_Bd[pn + 2*sN];
    float a0 = 0.f, a1 = 0.f, a2 = 0.f;
    for (int k = 0; k < KNNK; k++) {
        int j = ip[k];
        size_t pj = (size_t)(b * N3 + j) * Cout + c;
        float y0 = g_A[pj]        + bm0;
        float y1 = g_A[pj + sN]   + bm1;
        float y2 = g_A[pj + 2*sN] + bm2;
        float d0 = g_Ad[pj]        + bd0;
        float d1 = g_Ad[pj + sN]   + bd1;
        float d2 = g_Ad[pj + 2*sN] + bd2;
        float dm = fmaxf(sqrtf(d0*d0 + d1*d1 + d2*d2), EPSF);
        float k0 = d0/dm, k1 = d1/dm, k2 = d2/dm;
        float dot = y0*k0 + y1*k1 + y2*k2;
        float coef = (dot < 0.f) ? (-0.8f * dot) : 0.f;
        a0 += y0 + coef*k0; a1 += y1 + coef*k1; a2 += y2 + coef*k2;
    }
    const float s = 1.0f / 16.0f;
    size_t ob = ((size_t)(b * CATC + coff + c) * 3) * NN + n;
    g_cat[ob] = a0 * s; g_cat[ob + NN] = a1 * s; g_cat[ob + 2*NN] = a2 * s;
}

// ---- fused cc direction-dot + vec_act: one block per (b,n) ----
__global__ void ccfused_k(const float* __restrict__ ccD) {
    __shared__ float sk[3];
    int bn = blockIdx.x;
    int b = bn >> 10, n = bn & (NN - 1);
    int tid = threadIdx.x;
    int w = tid >> 5, lane = tid & 31;
    if (w < 3) {
        int cid = b * N3 + w * NN + n;
        const float* u = g_U + (size_t)cid * 128;
        float s = 0.f;
#pragma unroll
        for (int i = 0; i < 4; i++) s += ccD[i*32 + lane] * u[i*32 + lane];
        for (int off = 16; off > 0; off >>= 1)
            s += __shfl_down_sync(0xffffffffu, s, off);
        if (lane == 0) sk[w] = s;
    }
    __syncthreads();
    float d0 = sk[0], d1 = sk[1], d2 = sk[2];
    float dm = fmaxf(sqrtf(d0*d0 + d1*d1 + d2*d2), EPSF);
    float k0 = d0/dm, k1 = d1/dm, k2 = d2/dm;
    int bn0 = b * N3 + n;
    size_t sN = (size_t)NN * 128;
    size_t p = (size_t)bn0 * 128 + tid;
    float u0 = g_U[p], u1 = g_U[p + sN], u2 = g_U[p + 2*sN];
    float dot = u0*k0 + u1*k1 + u2*k2;
    float coef = (dot < 0.f) ? (-0.8f * dot) : 0.f;
    size_t ob = ((size_t)(b * 128 + tid) * 3) * NN + n;
    g_ycc[ob] = u0 + coef*k0; g_ycc[ob + NN] = u1 + coef*k1; g_ycc[ob + 2*NN] = u2 + coef*k2;
}

// ---- mean over N ----
__global__ void reduce_k() {
    __shared__ float s[256];
    const float* p = g_ycc + (size_t)blockIdx.x * NN;
    int t = threadIdx.x;
    s[t] = p[t] + p[t + 256] + p[t + 512] + p[t + 768];
    __syncthreads();
    for (int off = 128; off > 0; off >>= 1) {
        if (t < off) s[t] += s[t + off];
        __syncthreads();
    }
    if (t == 0) g_y[blockIdx.x] = s[0] * (1.0f / NN);
}

// ---- head helpers ----
__device__ __forceinline__ float bsum128(float v, float* s) {
    int t = threadIdx.x;
    s[t] = v; __syncthreads();
    for (int off = 64; off > 0; off >>= 1) {
        if (t < off) s[t] += s[t + off];
        __syncthreads();
    }
    float r = s[0]; __syncthreads();
    return r;
}
__device__ __forceinline__ void gemm3(float (*dst)[3], const float* W,
                                      const float (*src)[3], int Cout, int Cin, int c) {
    if (c < Cout) {
        float a0 = 0.f, a1 = 0.f, a2 = 0.f;
        for (int m = 0; m < Cin; m++) {
            float w = W[c * Cin + m];
            a0 += w * src[m][0]; a1 += w * src[m][1]; a2 += w * src[m][2];
        }
        dst[c][0] = a0; dst[c][1] = a1; dst[c][2] = a2;
    }
}
__device__ __forceinline__ void act_sq(float (*dst)[3], const float (*x)[3],
                                       const float* Wd, int C, int c) {
    if (c < C) {
        float d0 = 0.f, d1 = 0.f, d2 = 0.f;
        for (int m = 0; m < C; m++) {
            float w = Wd[c * C + m];
            d0 += w * x[m][0]; d1 += w * x[m][1]; d2 += w * x[m][2];
        }
        float dm = fmaxf(sqrtf(d0*d0 + d1*d1 + d2*d2), EPSF);
        float k0 = d0/dm, k1 = d1/dm, k2 = d2/dm;
        float dot = x[c][0]*k0 + x[c][1]*k1 + x[c][2]*k2;
        float coef = (dot < 0.f) ? (-0.8f * dot) : 0.f;
        dst[c][0] = x[c][0] + coef*k0;
        dst[c][1] = x[c][1] + coef*k1;
        dst[c][2] = x[c][2] + coef*k2;
    }
}

__global__ void head_k(const float* __restrict__ fcO,
                       const float* __restrict__ rbDin, const float* __restrict__ rbW0,
                       const float* __restrict__ rbDh,  const float* __restrict__ rbW1,
                       const float* __restrict__ rbWs,
                       const float* __restrict__ m0W, const float* __restrict__ m0D,
                       const float* __restrict__ m1W, const float* __restrict__ m1D,
                       const float* __restrict__ l0W, const float* __restrict__ l0D,
                       const float* __restrict__ l1W, const float* __restrict__ l1D,
                       const float* __restrict__ fimW, const float* __restrict__ filW,
                       float* __restrict__ out) {
    int b = blockIdx.x, c = threadIdx.x;
    __shared__ float sy[128][3], syn[128][3], t0[128][3], t1[128][3], t2[128][3];
    __shared__ float sred[128];
    __shared__ float sR[9];

    float y0 = g_y[(b*128 + c)*3 + 0];
    float y1 = g_y[(b*128 + c)*3 + 1];
    float y2 = g_y[(b*128 + c)*3 + 2];
    sy[c][0] = y0; sy[c][1] = y1; sy[c][2] = y2;
    float nc = sqrtf(y0*y0 + y1*y1 + y2*y2);
    __syncthreads();

    // scale
    float ss = bsum128(nc + EPSF, sred);
    if (c == 0) out[1060 + b] = ss * (1.0f / 128.0f) * 640.0f;

    // cevn(y)
    float S = bsum128(nc * nc, sred);
    float nn = nc / fmaxf(sqrtf(S), EPSF);
    float invn = fmaxf(nc, EPSF);
    syn[c][0] = y0/invn*nn; syn[c][1] = y1/invn*nn; syn[c][2] = y2/invn*nn;
    __syncthreads();

    // R[d][o] = sum_c fcO[o][c]*syn[c][d]
    for (int o = 0; o < 3; o++) {
        float wo = fcO[o * 128 + c];
        for (int d = 0; d < 3; d++) {
            float r = bsum128(wo * syn[c][d], sred);
            if (c == 0) sR[d*3 + o] = r;
        }
    }
    __syncthreads();

    // polar (det-scaled Newton); so3_out = transpose(Q)
    if (c == 0) {
        float X[9], Cf[9];
        float fn = 0.f;
        for (int i = 0; i < 9; i++) { X[i] = sR[i]; fn += X[i]*X[i]; }
        fn = sqrtf(fn); if (fn < 1e-20f) fn = 1e-20f;
        for (int i = 0; i < 9; i++) X[i] /= fn;
        for (int it = 0; it < 25; it++) {
            Cf[0] =  (X[4]*X[8] - X[5]*X[7]);
            Cf[1] = -(X[3]*X[8] - X[5]*X[6]);
            Cf[2] =  (X[3]*X[7] - X[4]*X[6]);
            Cf[3] = -(X[1]*X[8] - X[2]*X[7]);
            Cf[4] =  (X[0]*X[8] - X[2]*X[6]);
            Cf[5] = -(X[0]*X[7] - X[1]*X[6]);
            Cf[6] =  (X[1]*X[5] - X[2]*X[4]);
            Cf[7] = -(X[0]*X[5] - X[2]*X[3]);
            Cf[8] =  (X[0]*X[4] - X[1]*X[3]);
            float det = X[0]*Cf[0] + X[1]*Cf[1] + X[2]*Cf[2];
            float ad = fabsf(det);
            if (ad < 1e-30f) break;
            float z = 1.0f / cbrtf(ad);
            float invd = 1.0f / det;
            for (int i = 0; i < 9; i++)
                X[i] = 0.5f * (z * X[i] + (Cf[i] * invd) / z);
        }
        for (int i = 0; i < 3; i++)
            for (int j = 0; j < 3; j++)
                out[1024 + b*9 + i*3 + j] = X[j*3 + i];
    }

    // residual block: center
    act_sq(t0, sy, rbDin, 128, c);
    __syncthreads();
    gemm3(t1, rbW0, t0, 64, 128, c);
    __syncthreads();
    act_sq(t2, t1, rbDh, 64, c);
    __syncthreads();
    if (c < 3) {
        float dx = 0.f;
        for (int m = 0; m < 64; m++) dx += rbW1[m] * t2[m][c];
        float wsv = 0.f;
        for (int m = 0; m < 128; m++) wsv += rbWs[m] * sy[m][c];
        out[1064 + b*3 + c] = (wsv + dx) * 640.0f;
    }
    __syncthreads();

    // mean branch
    gemm3(t0, m0W, syn, 128, 128, c); __syncthreads();
    act_sq(t1, t0, m0D, 128, c);      __syncthreads();
    gemm3(t0, m1W, t1, 128, 128, c);  __syncthreads();
    act_sq(t2, t0, m1D, 128, c);      __syncthreads();
    gemm3(t0, fimW, t2, 128, 128, c); __syncthreads();
    out[b*128 + c] = t2[c][0]*t0[c][0] + t2[c][1]*t0[c][1] + t2[c][2]*t0[c][2];
    __syncthreads();

    // logvar branch
    gemm3(t0, l0W, syn, 128, 128, c); __syncthreads();
    act_sq(t1, t0, l0D, 128, c);      __syncthreads();
    gemm3(t0, l1W, t1, 128, 128, c);  __syncthreads();
    act_sq(t2, t0, l1D, 128, c);      __syncthreads();
    gemm3(t0, filW, t2, 128, 128, c); __syncthreads();
    out[512 + b*128 + c] = t2[c][0]*t0[c][0] + t2[c][1]*t0[c][1] + t2[c][2]*t0[c][2];
}

// ---- host-side layer driver: 2 launches per layer ----
static void run_layer(const float* W, int layer, int Cin, int Cout,
                      const float* xin, int finoff, size_t bstride, int coff) {
    int wcols = 2 * Cin;
    int wpoff = layer * WPSLOT;
    dim3 g(24, 4 * (Cout / 8));
    size_t sm = (size_t)8 * Cin * sizeof(float);
    gemm4_k<<<g, 128, sm>>>(W, wpoff, wcols, xin, finoff, Cin, bstride, Cout);
    int P = 128 / Cout;
    edge_k<<<BB * NN / P, 128>>>(Cout, coff, P);
}

extern "C" void kernel_launch(void* const* d_in, const int* in_sizes, int n_in,
                              void* d_out, int out_size) {
    const float* x    = (const float*)d_in[0];
    const float* c1W  = (const float*)d_in[2];
    const float* c1D  = (const float*)d_in[3];
    const float* c2W  = (const float*)d_in[4];
    const float* c2D  = (const float*)d_in[5];
    const float* c3W  = (const float*)d_in[6];
    const float* c3D  = (const float*)d_in[7];
    const float* c4W  = (const float*)d_in[8];
    const float* c4D  = (const float*)d_in[9];
    const float* ccW  = (const float*)d_in[10];
    const float* ccD  = (const float*)d_in[11];
    const float* fcO  = (const float*)d_in[12];
    const float* m0W  = (const float*)d_in[13];
    const float* m0D  = (const float*)d_in[14];
    const float* m1W  = (const float*)d_in[15];
    const float* m1D  = (const float*)d_in[16];
    const float* l0W  = (const float*)d_in[17];
    const float* l0D  = (const float*)d_in[18];
    const float* l1W  = (const float*)d_in[19];
    const float* l1D  = (const float*)d_in[20];
    const float* fimW = (const float*)d_in[21];
    const float* filW = (const float*)d_in[22];
    const float* rbDin= (const float*)d_in[23];
    const float* rbW0 = (const float*)d_in[24];
    const float* rbDh = (const float*)d_in[25];
    const float* rbW1 = (const float*)d_in[26];
    const float* rbWs = (const float*)d_in[27];
    float* out = (float*)d_out;

    knn_k<<<BB * NN, 256>>>(x);
    wcomb_all_k<<<352, 256>>>(c1W, c1D, c2W, c2D, c3W, c3D, c4W, c4D);

    size_t catbs = (size_t)CATC * N3;
    run_layer(c1W, 0, 1,   32,  x,       0,        (size_t)N3, 0);
    run_layer(c2W, 1, 32,  64,  nullptr, 0,        catbs,      32);
    run_layer(c3W, 2, 64,  128, nullptr, 32 * N3,  catbs,      96);
    run_layer(c4W, 3, 128, 128, nullptr, 96 * N3,  catbs,      224);

    // cc layer
    {
        dim3 g(24, 16);
        size_t sm = (size_t)8 * CATC * sizeof(float);
        gemm_k<<<g, 128, sm>>>(ccW, CATC, CATC, catbs, 128);
    }
    ccfused_k<<<BB * NN, 128>>>(ccD);
    reduce_k<<<BB * 128 * 3, 256>>>();

    head_k<<<BB, 128>>>(fcO, rbDin, rbW0, rbDh, rbW1, rbWs,
                        m0W, m0D, m1W, m1D, l0W, l0D, l1W, l1D,
                        fimW, filW, out);
}

// round 12
// speedup vs baseline: 1.3958x; 1.0663x over previous
#include <cuda_runtime.h>
#include <math.h>

#define BB 4
#define NN 1024
#define KNNK 16
#define N3 3072
#define NCOL 12288
#define CATC 352
#define WPSLOT 32768
#define EPSF 1e-12f

// ---- static scratch ----
__device__ __align__(16) float g_cat[BB * CATC * 3 * NN];  // [b][c][d][n]
__device__ __align__(16) float g_A [NCOL * 128];           // [cid][o], cid=b*3N+d*N+n
__device__ __align__(16) float g_Bm[NCOL * 128];
__device__ __align__(16) float g_Ad[NCOL * 128];
__device__ __align__(16) float g_Bd[NCOL * 128];
__device__ __align__(16) float g_U [NCOL * 128];
__device__ __align__(16) float g_Wp[4 * WPSLOT];
__device__ __align__(16) float g_ycc[BB * 128 * 3 * NN];
__device__ __align__(16) float g_y[BB * 128 * 3];
__device__ int g_idx[BB * NN * KNNK];

// ---- fused KNN + weight-combine: one launch ----
// blocks [0, 4096): KNN (PROTECTED rounding structure — do not change)
// blocks [4096, 4448): Wp = Wd @ W for all 4 layers
__global__ void pre_k(const float* __restrict__ x,
                      const float* __restrict__ W1, const float* __restrict__ D1,
                      const float* __restrict__ W2, const float* __restrict__ D2,
                      const float* __restrict__ W3, const float* __restrict__ D3,
                      const float* __restrict__ W4, const float* __restrict__ D4) {
    __shared__ float ssq[NN];
    __shared__ float sd[NN];
    __shared__ float rv[8];
    __shared__ int   ri[8];
    if (blockIdx.x >= BB * NN) {
        int bid = blockIdx.x - BB * NN;
        const float *W, *Wd; int Cin, Cout, o, slot;
        if (bid < 32)       { W = W1; Wd = D1; Cin = 1;   Cout = 32;  o = bid;       slot = 0; }
        else if (bid < 96)  { W = W2; Wd = D2; Cin = 32;  Cout = 64;  o = bid - 32;  slot = 1; }
        else if (bid < 224) { W = W3; Wd = D3; Cin = 64;  Cout = 128; o = bid - 96;  slot = 2; }
        else                { W = W4; Wd = D4; Cin = 128; Cout = 128; o = bid - 224; slot = 3; }
        int wcols = 2 * Cin;
        int j = threadIdx.x;
        if (j >= wcols) return;
        float s = 0.f;
        for (int m = 0; m < Cout; m++) s += Wd[o * Cout + m] * W[m * wcols + j];
        g_Wp[slot * WPSLOT + o * wcols + j] = s;
        return;
    }
    int bn = blockIdx.x;
    int b = bn >> 10, n = bn & (NN - 1);
    int tid = threadIdx.x;
    const float* xb = x + (size_t)b * N3;
    for (int m = tid; m < NN; m += 256) {
        float qx = xb[m], qy = xb[NN + m], qz = xb[2*NN + m];
        ssq[m] = __fadd_rn(__fadd_rn(__fmul_rn(qx, qx), __fmul_rn(qy, qy)),
                           __fmul_rn(qz, qz));
    }
    __syncthreads();
    float px = xb[n], py = xb[NN + n], pz = xb[2*NN + n];
    float sqn = ssq[n];
    for (int m = tid; m < NN; m += 256) {
        float qx = xb[m], qy = xb[NN + m], qz = xb[2*NN + m];
        float dot = __fmaf_rn(pz, qz, __fmaf_rn(py, qy, __fmul_rn(px, qx)));
        sd[m] = __fsub_rn(__fadd_rn(sqn, ssq[m]), __fmul_rn(2.0f, dot));
    }
    __syncthreads();
    for (int k = 0; k < KNNK; k++) {
        float bv = INFINITY; int bi = 0x7fffffff;
        for (int m = tid; m < NN; m += 256) {
            float v = sd[m];
            if (v < bv || (v == bv && m < bi)) { bv = v; bi = m; }
        }
        for (int off = 16; off > 0; off >>= 1) {
            float ov = __shfl_down_sync(0xffffffffu, bv, off);
            int   oi = __shfl_down_sync(0xffffffffu, bi, off);
            if (ov < bv || (ov == bv && oi < bi)) { bv = ov; bi = oi; }
        }
        if ((tid & 31) == 0) { rv[tid >> 5] = bv; ri[tid >> 5] = bi; }
        __syncthreads();
        if (tid == 0) {
            float fv = rv[0]; int fi = ri[0];
            for (int w = 1; w < 8; w++)
                if (rv[w] < fv || (rv[w] == fv && ri[w] < fi)) { fv = rv[w]; fi = ri[w]; }
            g_idx[bn * KNNK + k] = fi;
            sd[fi] = INFINITY;
        }
        __syncthreads();
    }
}

// ---- output selector: 0 A (W,m0), 1 Bm (W,m1), 2 Ad (Wp,m0), 3 Bd (Wp,m1) ----
__device__ __forceinline__ float* out_sel(int s) {
    switch (s) {
        case 0: return g_A;
        case 1: return g_Bm;
        case 2: return g_Ad;
        default: return g_Bd;
    }
}

// ---- fused 4-way skinny GEMM: 8 cols/thread, one launch per layer ----
__global__ void gemm4_k(const float* __restrict__ Wparam, int wpoff, int ldw,
                        const float* __restrict__ xin, int finoff,
                        int Cin, size_t bstride, int Cout) {
    extern __shared__ float ws[];
    const int R = 8;
    int groups = Cout >> 3;
    int which = blockIdx.y / groups;          // 0..3
    int o0 = (blockIdx.y - which * groups) * R;
    int mode = which & 1;
    const float* W = (which & 2) ? (g_Wp + wpoff) : Wparam;
    float* OUT = out_sel(which);
    for (int t = threadIdx.x; t < R * Cin; t += blockDim.x) {
        int i = t / Cin, c = t - i * Cin;
        float w = W[(o0 + i) * ldw + c];
        if (mode) w = W[(o0 + i) * ldw + Cin + c] - w;
        ws[t] = w;
    }
    __syncthreads();
    const float* FIN = xin ? xin : (g_cat + finoff);
    int cid = (blockIdx.x * blockDim.x + threadIdx.x) * 8;
    int b = cid / N3;
    int dn = cid - b * N3;
    const float* fin = FIN + (size_t)b * bstride + dn;
    float acc[8][8];
#pragma unroll
    for (int i = 0; i < 8; i++)
#pragma unroll
        for (int j = 0; j < 8; j++) acc[i][j] = 0.f;
    for (int c = 0; c < Cin; c++) {
        const float* fp = fin + (size_t)c * N3;
        float4 fa = *reinterpret_cast<const float4*>(fp);
        float4 fb = *reinterpret_cast<const float4*>(fp + 4);
#pragma unroll
        for (int i = 0; i < 8; i++) {
            float w = ws[i * Cin + c];
            acc[i][0] += w * fa.x; acc[i][1] += w * fa.y;
            acc[i][2] += w * fa.z; acc[i][3] += w * fa.w;
            acc[i][4] += w * fb.x; acc[i][5] += w * fb.y;
            acc[i][6] += w * fb.z; acc[i][7] += w * fb.w;
        }
    }
#pragma unroll
    for (int j = 0; j < 8; j++) {
        float* op = OUT + (size_t)(cid + j) * Cout + o0;
        float4 v0 = make_float4(acc[0][j], acc[1][j], acc[2][j], acc[3][j]);
        float4 v1 = make_float4(acc[4][j], acc[5][j], acc[6][j], acc[7][j]);
        *(float4*)op = v0; *(float4*)(op + 4) = v1;
    }
}

// ---- cc skinny GEMM (single output set, 8 cols/thread) ----
__global__ void gemm_k(const float* __restrict__ Wparam,
                       int ldw, int Cin, size_t bstride, int Cout) {
    extern __shared__ float ws[];
    const int R = 8;
    int o0 = blockIdx.y * R;
    for (int t = threadIdx.x; t < R * Cin; t += blockDim.x) {
        int i = t / Cin, c = t - i * Cin;
        ws[t] = Wparam[(o0 + i) * ldw + c];
    }
    __syncthreads();
    int cid = (blockIdx.x * blockDim.x + threadIdx.x) * 8;
    int b = cid / N3;
    int dn = cid - b * N3;
    const float* fin = g_cat + (size_t)b * bstride + dn;
    float acc[8][8];
#pragma unroll
    for (int i = 0; i < 8; i++)
#pragma unroll
        for (int j = 0; j < 8; j++) acc[i][j] = 0.f;
    for (int c = 0; c < Cin; c++) {
        const float* fp = fin + (size_t)c * N3;
        float4 fa = *reinterpret_cast<const float4*>(fp);
        float4 fb = *reinterpret_cast<const float4*>(fp + 4);
#pragma unroll
        for (int i = 0; i < 8; i++) {
            float w = ws[i * Cin + c];
            acc[i][0] += w * fa.x; acc[i][1] += w * fa.y;
            acc[i][2] += w * fa.z; acc[i][3] += w * fa.w;
            acc[i][4] += w * fb.x; acc[i][5] += w * fb.y;
            acc[i][6] += w * fb.z; acc[i][7] += w * fb.w;
        }
    }
#pragma unroll
    for (int j = 0; j < 8; j++) {
        float* op = g_U + (size_t)(cid + j) * Cout + o0;
        float4 v0 = make_float4(acc[0][j], acc[1][j], acc[2][j], acc[3][j]);
        float4 v1 = make_float4(acc[4][j], acc[5][j], acc[6][j], acc[7][j]);
        *(float4*)op = v0; *(float4*)(op + 4) = v1;
    }
}

// ---- edge: gather + vec_act + mean over K (P points per block) ----
__global__ void edge_k(int Cout, int coff, int P) {
    int tid = threadIdx.x;
    int p = tid / Cout;
    int c = tid - p * Cout;
    int bn = blockIdx.x * P + p;
    int b = bn >> 10, n = bn & (NN - 1);
    const int* ip = g_idx + bn * KNNK;
    int bn0 = b * N3 + n;
    size_t sN = (size_t)NN * Cout;
    size_t pn = (size_t)bn0 * Cout + c;
    float bm0 = g_Bm[pn], bm1 = g_Bm[pn + sN], bm2 = g_Bm[pn + 2*sN];
    float bd0 = g_Bd[pn], bd1 = g_Bd[pn + sN], bd2 = g_Bd[pn + 2*sN];
    float a0 = 0.f, a1 = 0.f, a2 = 0.f;
    for (int k = 0; k < KNNK; k++) {
        int j = ip[k];
        size_t pj = (size_t)(b * N3 + j) * Cout + c;
        float y0 = g_A[pj]        + bm0;
        float y1 = g_A[pj + sN]   + bm1;
        float y2 = g_A[pj + 2*sN] + bm2;
        float d0 = g_Ad[pj]        + bd0;
        float d1 = g_Ad[pj + sN]   + bd1;
        float d2 = g_Ad[pj + 2*sN] + bd2;
        float dm = fmaxf(sqrtf(d0*d0 + d1*d1 + d2*d2), EPSF);
        float k0 = d0/dm, k1 = d1/dm, k2 = d2/dm;
        float dot = y0*k0 + y1*k1 + y2*k2;
        float coef = (dot < 0.f) ? (-0.8f * dot) : 0.f;
        a0 += y0 + coef*k0; a1 += y1 + coef*k1; a2 += y2 + coef*k2;
    }
    const float s = 1.0f / 16.0f;
    size_t ob = ((size_t)(b * CATC + coff + c) * 3) * NN + n;
    g_cat[ob] = a0 * s; g_cat[ob + NN] = a1 * s; g_cat[ob + 2*NN] = a2 * s;
}

// ---- fused cc direction-dot + vec_act: one block per (b,n) ----
__global__ void ccfused_k(const float* __restrict__ ccD) {
    __shared__ float sk[3];
    int bn = blockIdx.x;
    int b = bn >> 10, n = bn & (NN - 1);
    int tid = threadIdx.x;
    int w = tid >> 5, lane = tid & 31;
    if (w < 3) {
        int cid = b * N3 + w * NN + n;
        const float* u = g_U + (size_t)cid * 128;
        float s = 0.f;
#pragma unroll
        for (int i = 0; i < 4; i++) s += ccD[i*32 + lane] * u[i*32 + lane];
        for (int off = 16; off > 0; off >>= 1)
            s += __shfl_down_sync(0xffffffffu, s, off);
        if (lane == 0) sk[w] = s;
    }
    __syncthreads();
    float d0 = sk[0], d1 = sk[1], d2 = sk[2];
    float dm = fmaxf(sqrtf(d0*d0 + d1*d1 + d2*d2), EPSF);
    float k0 = d0/dm, k1 = d1/dm, k2 = d2/dm;
    int bn0 = b * N3 + n;
    size_t sN = (size_t)NN * 128;
    size_t p = (size_t)bn0 * 128 + tid;
    float u0 = g_U[p], u1 = g_U[p + sN], u2 = g_U[p + 2*sN];
    float dot = u0*k0 + u1*k1 + u2*k2;
    float coef = (dot < 0.f) ? (-0.8f * dot) : 0.f;
    size_t ob = ((size_t)(b * 128 + tid) * 3) * NN + n;
    g_ycc[ob] = u0 + coef*k0; g_ycc[ob + NN] = u1 + coef*k1; g_ycc[ob + 2*NN] = u2 + coef*k2;
}

// ---- mean over N ----
__global__ void reduce_k() {
    __shared__ float s[256];
    const float* p = g_ycc + (size_t)blockIdx.x * NN;
    int t = threadIdx.x;
    s[t] = p[t] + p[t + 256] + p[t + 512] + p[t + 768];
    __syncthreads();
    for (int off = 128; off > 0; off >>= 1) {
        if (t < off) s[t] += s[t + off];
        __syncthreads();
    }
    if (t == 0) g_y[blockIdx.x] = s[0] * (1.0f / NN);
}

// ---- head helpers ----
__device__ __forceinline__ float bsum128(float v, float* s) {
    int t = threadIdx.x;
    s[t] = v; __syncthreads();
    for (int off = 64; off > 0; off >>= 1) {
        if (t < off) s[t] += s[t + off];
        __syncthreads();
    }
    float r = s[0]; __syncthreads();
    return r;
}
__device__ __forceinline__ void gemm3(float (*dst)[3], const float* W,
                                      const float (*src)[3], int Cout, int Cin, int c) {
    if (c < Cout) {
        float a0 = 0.f, a1 = 0.f, a2 = 0.f;
        for (int m = 0; m < Cin; m++) {
            float w = W[c * Cin + m];
            a0 += w * src[m][0]; a1 += w * src[m][1]; a2 += w * src[m][2];
        }
        dst[c][0] = a0; dst[c][1] = a1; dst[c][2] = a2;
    }
}
__device__ __forceinline__ void act_sq(float (*dst)[3], const float (*x)[3],
                                       const float* Wd, int C, int c) {
    if (c < C) {
        float d0 = 0.f, d1 = 0.f, d2 = 0.f;
        for (int m = 0; m < C; m++) {
            float w = Wd[c * C + m];
            d0 += w * x[m][0]; d1 += w * x[m][1]; d2 += w * x[m][2];
        }
        float dm = fmaxf(sqrtf(d0*d0 + d1*d1 + d2*d2), EPSF);
        float k0 = d0/dm, k1 = d1/dm, k2 = d2/dm;
        float dot = x[c][0]*k0 + x[c][1]*k1 + x[c][2]*k2;
        float coef = (dot < 0.f) ? (-0.8f * dot) : 0.f;
        dst[c][0] = x[c][0] + coef*k0;
        dst[c][1] = x[c][1] + coef*k1;
        dst[c][2] = x[c][2] + coef*k2;
    }
}

// ---- head: 2 blocks per batch (branch 0: scale/R/polar/residual/mean; 1: logvar) ----
__global__ void head_k(const float* __restrict__ fcO,
                       const float* __restrict__ rbDin, const float* __restrict__ rbW0,
                       const float* __restrict__ rbDh,  const float* __restrict__ rbW1,
                       const float* __restrict__ rbWs,
                       const float* __restrict__ m0W, const float* __restrict__ m0D,
                       const float* __restrict__ m1W, const float* __restrict__ m1D,
                       const float* __restrict__ l0W, const float* __restrict__ l0D,
                       const float* __restrict__ l1W, const float* __restrict__ l1D,
                       const float* __restrict__ fimW, const float* __restrict__ filW,
                       float* __restrict__ out) {
    int b = blockIdx.x >> 1;
    int branch = blockIdx.x & 1;
    int c = threadIdx.x;
    __shared__ float sy[128][3], syn[128][3], t0[128][3], t1[128][3], t2[128][3];
    __shared__ float sred[128];
    __shared__ float sR[9];

    float y0 = g_y[(b*128 + c)*3 + 0];
    float y1 = g_y[(b*128 + c)*3 + 1];
    float y2 = g_y[(b*128 + c)*3 + 2];
    sy[c][0] = y0; sy[c][1] = y1; sy[c][2] = y2;
    float nc = sqrtf(y0*y0 + y1*y1 + y2*y2);
    __syncthreads();

    if (branch == 0) {
        // scale
        float ss = bsum128(nc + EPSF, sred);
        if (c == 0) out[1060 + b] = ss * (1.0f / 128.0f) * 640.0f;
    }

    // cevn(y) (both branches need syn)
    float S = bsum128(nc * nc, sred);
    float nn = nc / fmaxf(sqrtf(S), EPSF);
    float invn = fmaxf(nc, EPSF);
    syn[c][0] = y0/invn*nn; syn[c][1] = y1/invn*nn; syn[c][2] = y2/invn*nn;
    __syncthreads();

    if (branch == 0) {
        // R[d][o] = sum_c fcO[o][c]*syn[c][d]
        for (int o = 0; o < 3; o++) {
            float wo = fcO[o * 128 + c];
            for (int d = 0; d < 3; d++) {
                float r = bsum128(wo * syn[c][d], sred);
                if (c == 0) sR[d*3 + o] = r;
            }
        }
        __syncthreads();

        // polar (det-scaled Newton); so3_out = transpose(Q)
        if (c == 0) {
            float X[9], Cf[9];
            float fn = 0.f;
            for (int i = 0; i < 9; i++) { X[i] = sR[i]; fn += X[i]*X[i]; }
            fn = sqrtf(fn); if (fn < 1e-20f) fn = 1e-20f;
            for (int i = 0; i < 9; i++) X[i] /= fn;
            for (int it = 0; it < 25; it++) {
                Cf[0] =  (X[4]*X[8] - X[5]*X[7]);
                Cf[1] = -(X[3]*X[8] - X[5]*X[6]);
                Cf[2] =  (X[3]*X[7] - X[4]*X[6]);
                Cf[3] = -(X[1]*X[8] - X[2]*X[7]);
                Cf[4] =  (X[0]*X[8] - X[2]*X[6]);
                Cf[5] = -(X[0]*X[7] - X[1]*X[6]);
                Cf[6] =  (X[1]*X[5] - X[2]*X[4]);
                Cf[7] = -(X[0]*X[5] - X[2]*X[3]);
                Cf[8] =  (X[0]*X[4] - X[1]*X[3]);
                float det = X[0]*Cf[0] + X[1]*Cf[1] + X[2]*Cf[2];
                float ad = fabsf(det);
                if (ad < 1e-30f) break;
                float z = 1.0f / cbrtf(ad);
                float invd = 1.0f / det;
                for (int i = 0; i < 9; i++)
                    X[i] = 0.5f * (z * X[i] + (Cf[i] * invd) / z);
            }
            for (int i = 0; i < 3; i++)
                for (int j = 0; j < 3; j++)
                    out[1024 + b*9 + i*3 + j] = X[j*3 + i];
        }

        // residual block: center
        act_sq(t0, sy, rbDin, 128, c);
        __syncthreads();
        gemm3(t1, rbW0, t0, 64, 128, c);
        __syncthreads();
        act_sq(t2, t1, rbDh, 64, c);
        __syncthreads();
        if (c < 3) {
            float dx = 0.f;
            for (int m = 0; m < 64; m++) dx += rbW1[m] * t2[m][c];
            float wsv = 0.f;
            for (int m = 0; m < 128; m++) wsv += rbWs[m] * sy[m][c];
            out[1064 + b*3 + c] = (wsv + dx) * 640.0f;
        }
        __syncthreads();

        // mean branch
        gemm3(t0, m0W, syn, 128, 128, c); __syncthreads();
        act_sq(t1, t0, m0D, 128, c);      __syncthreads();
        gemm3(t0, m1W, t1, 128, 128, c);  __syncthreads();
        act_sq(t2, t0, m1D, 128, c);      __syncthreads();
        gemm3(t0, fimW, t2, 128, 128, c); __syncthreads();
        out[b*128 + c] = t2[c][0]*t0[c][0] + t2[c][1]*t0[c][1] + t2[c][2]*t0[c][2];
    } else {
        // logvar branch
        gemm3(t0, l0W, syn, 128, 128, c); __syncthreads();
        act_sq(t1, t0, l0D, 128, c);      __syncthreads();
        gemm3(t0, l1W, t1, 128, 128, c);  __syncthreads();
        act_sq(t2, t0, l1D, 128, c);      __syncthreads();
        gemm3(t0, filW, t2, 128, 128, c); __syncthreads();
        out[512 + b*128 + c] = t2[c][0]*t0[c][0] + t2[c][1]*t0[c][1] + t2[c][2]*t0[c][2];
    }
}

// ---- host-side layer driver: 2 launches per layer ----
static void run_layer(const float* W, int layer, int Cin, int Cout,
                      const float* xin, int finoff, size_t bstride, int coff) {
    int wcols = 2 * Cin;
    int wpoff = layer * WPSLOT;
    dim3 g(12, 4 * (Cout / 8));
    size_t sm = (size_t)8 * Cin * sizeof(float);
    gemm4_k<<<g, 128, sm>>>(W, wpoff, wcols, xin, finoff, Cin, bstride, Cout);
    int P = 128 / Cout;
    edge_k<<<BB * NN / P, 128>>>(Cout, coff, P);
}

extern "C" void kernel_launch(void* const* d_in, const int* in_sizes, int n_in,
                              void* d_out, int out_size) {
    const float* x    = (const float*)d_in[0];
    const float* c1W  = (const float*)d_in[2];
    const float* c1D  = (const float*)d_in[3];
    const float* c2W  = (const float*)d_in[4];
    const float* c2D  = (const float*)d_in[5];
    const float* c3W  = (const float*)d_in[6];
    const float* c3D  = (const float*)d_in[7];
    const float* c4W  = (const float*)d_in[8];
    const float* c4D  = (const float*)d_in[9];
    const float* ccW  = (const float*)d_in[10];
    const float* ccD  = (const float*)d_in[11];
    const float* fcO  = (const float*)d_in[12];
    const float* m0W  = (const float*)d_in[13];
    const float* m0D  = (const float*)d_in[14];
    const float* m1W  = (const float*)d_in[15];
    const float* m1D  = (const float*)d_in[16];
    const float* l0W  = (const float*)d_in[17];
    const float* l0D  = (const float*)d_in[18];
    const float* l1W  = (const float*)d_in[19];
    const float* l1D  = (const float*)d_in[20];
    const float* fimW = (const float*)d_in[21];
    const float* filW = (const float*)d_in[22];
    const float* rbDin= (const float*)d_in[23];
    const float* rbW0 = (const float*)d_in[24];
    const float* rbDh = (const float*)d_in[25];
    const float* rbW1 = (const float*)d_in[26];
    const float* rbWs = (const float*)d_in[27];
    float* out = (float*)d_out;

    pre_k<<<BB * NN + 352, 256>>>(x, c1W, c1D, c2W, c2D, c3W, c3D, c4W, c4D);

    size_t catbs = (size_t)CATC * N3;
    run_layer(c1W, 0, 1,   32,  x,       0,        (size_t)N3, 0);
    run_layer(c2W, 1, 32,  64,  nullptr, 0,        catbs,      32);
    run_layer(c3W, 2, 64,  128, nullptr, 32 * N3,  catbs,      96);
    run_layer(c4W, 3, 128, 128, nullptr, 96 * N3,  catbs,      224);

    // cc layer
    {
        dim3 g(12, 16);
        size_t sm = (size_t)8 * CATC * sizeof(float);
        gemm_k<<<g, 128, sm>>>(ccW, CATC, CATC, catbs, 128);
    }
    ccfused_k<<<BB * NN, 128>>>(ccD);
    reduce_k<<<BB * 128 * 3, 256>>>();

    head_k<<<BB * 2, 128>>>(fcO, rbDin, rbW0, rbDh, rbW1, rbWs,
                            m0W, m0D, m1W, m1D, l0W, l0D, l1W, l1D,
                            fimW, filW, out);
}

// round 13
// speedup vs baseline: 1.4695x; 1.0527x over previous
#include <cuda_runtime.h>
#include <math.h>

#define BB 4
#define NN 1024
#define KNNK 16
#define N3 3072
#define NCOL 12288
#define CATC 352
#define WPSLOT 32768
#define EPSF 1e-12f

// ---- static scratch ----
__device__ __align__(16) float g_cat[BB * CATC * 3 * NN];  // [b][c][d][n]
__device__ __align__(16) float g_A [NCOL * 128];           // [cid][o], cid=b*3N+d*N+n
__device__ __align__(16) float g_Bm[NCOL * 128];
__device__ __align__(16) float g_Ad[NCOL * 128];
__device__ __align__(16) float g_Bd[NCOL * 128];
__device__ __align__(16) float g_U [NCOL * 128];
__device__ __align__(16) float g_Wp[4 * WPSLOT];
__device__ __align__(16) float g_ycc[BB * 128 * 3 * NN];
__device__ __align__(16) float g_y[BB * 128 * 3];
__device__ int g_idx[BB * NN * KNNK];

// ---- fused KNN + weight-combine: one launch ----
// blocks [0, 4096): KNN (PROTECTED rounding structure — do not change)
// blocks [4096, 4448): Wp = Wd @ W for all 4 layers
__global__ void pre_k(const float* __restrict__ x,
                      const float* __restrict__ W1, const float* __restrict__ D1,
                      const float* __restrict__ W2, const float* __restrict__ D2,
                      const float* __restrict__ W3, const float* __restrict__ D3,
                      const float* __restrict__ W4, const float* __restrict__ D4) {
    __shared__ float ssq[NN];
    __shared__ float sd[NN];
    __shared__ float rv[8];
    __shared__ int   ri[8];
    if (blockIdx.x >= BB * NN) {
        int bid = blockIdx.x - BB * NN;
        const float *W, *Wd; int Cin, Cout, o, slot;
        if (bid < 32)       { W = W1; Wd = D1; Cin = 1;   Cout = 32;  o = bid;       slot = 0; }
        else if (bid < 96)  { W = W2; Wd = D2; Cin = 32;  Cout = 64;  o = bid - 32;  slot = 1; }
        else if (bid < 224) { W = W3; Wd = D3; Cin = 64;  Cout = 128; o = bid - 96;  slot = 2; }
        else                { W = W4; Wd = D4; Cin = 128; Cout = 128; o = bid - 224; slot = 3; }
        int wcols = 2 * Cin;
        int j = threadIdx.x;
        if (j >= wcols) return;
        float s = 0.f;
        for (int m = 0; m < Cout; m++) s += Wd[o * Cout + m] * W[m * wcols + j];
        g_Wp[slot * WPSLOT + o * wcols + j] = s;
        return;
    }
    int bn = blockIdx.x;
    int b = bn >> 10, n = bn & (NN - 1);
    int tid = threadIdx.x;
    const float* xb = x + (size_t)b * N3;
    for (int m = tid; m < NN; m += 256) {
        float qx = xb[m], qy = xb[NN + m], qz = xb[2*NN + m];
        ssq[m] = __fadd_rn(__fadd_rn(__fmul_rn(qx, qx), __fmul_rn(qy, qy)),
                           __fmul_rn(qz, qz));
    }
    __syncthreads();
    float px = xb[n], py = xb[NN + n], pz = xb[2*NN + n];
    float sqn = ssq[n];
    for (int m = tid; m < NN; m += 256) {
        float qx = xb[m], qy = xb[NN + m], qz = xb[2*NN + m];
        float dot = __fmaf_rn(pz, qz, __fmaf_rn(py, qy, __fmul_rn(px, qx)));
        sd[m] = __fsub_rn(__fadd_rn(sqn, ssq[m]), __fmul_rn(2.0f, dot));
    }
    __syncthreads();
    for (int k = 0; k < KNNK; k++) {
        float bv = INFINITY; int bi = 0x7fffffff;
        for (int m = tid; m < NN; m += 256) {
            float v = sd[m];
            if (v < bv || (v == bv && m < bi)) { bv = v; bi = m; }
        }
        for (int off = 16; off > 0; off >>= 1) {
            float ov = __shfl_down_sync(0xffffffffu, bv, off);
            int   oi = __shfl_down_sync(0xffffffffu, bi, off);
            if (ov < bv || (ov == bv && oi < bi)) { bv = ov; bi = oi; }
        }
        if ((tid & 31) == 0) { rv[tid >> 5] = bv; ri[tid >> 5] = bi; }
        __syncthreads();
        if (tid == 0) {
            float fv = rv[0]; int fi = ri[0];
            for (int w = 1; w < 8; w++)
                if (rv[w] < fv || (rv[w] == fv && ri[w] < fi)) { fv = rv[w]; fi = ri[w]; }
            g_idx[bn * KNNK + k] = fi;
            sd[fi] = INFINITY;
        }
        __syncthreads();
    }
}

// ---- output selector ----
__device__ __forceinline__ float* out_sel(int s) {
    switch (s) {
        case 0: return g_A;
        case 1: return g_Bm;
        case 2: return g_Ad;
        default: return g_Bd;
    }
}

// ---- fused 4-way skinny GEMM: software-pipelined, 256 threads ----
__global__ __launch_bounds__(256)
void gemm4_k(const float* __restrict__ Wparam, int wpoff, int ldw,
             const float* __restrict__ xin, int finoff,
             int Cin, size_t bstride, int Cout) {
    extern __shared__ float ws[];
    const int R = 8;
    int groups = Cout >> 3;
    int which = blockIdx.y / groups;          // 0..3
    int o0 = (blockIdx.y - which * groups) * R;
    int mode = which & 1;
    const float* W = (which & 2) ? (g_Wp + wpoff) : Wparam;
    float* OUT = out_sel(which);
    for (int t = threadIdx.x; t < R * Cin; t += blockDim.x) {
        int i = t / Cin, c = t - i * Cin;
        float w = W[(o0 + i) * ldw + c];
        if (mode) w = W[(o0 + i) * ldw + Cin + c] - w;
        ws[t] = w;
    }
    __syncthreads();
    const float* FIN = xin ? xin : (g_cat + finoff);
    int cid = (blockIdx.x * blockDim.x + threadIdx.x) * 8;
    int b = cid / N3;
    int dn = cid - b * N3;
    const float* fin = FIN + (size_t)b * bstride + dn;
    float acc[8][8];
#pragma unroll
    for (int i = 0; i < 8; i++)
#pragma unroll
        for (int j = 0; j < 8; j++) acc[i][j] = 0.f;
    float4 fa = *reinterpret_cast<const float4*>(fin);
    float4 fb = *reinterpret_cast<const float4*>(fin + 4);
#pragma unroll 2
    for (int c = 0; c < Cin; c++) {
        float4 na, nb;
        if (c + 1 < Cin) {
            const float* np = fin + (size_t)(c + 1) * N3;
            na = *reinterpret_cast<const float4*>(np);
            nb = *reinterpret_cast<const float4*>(np + 4);
        }
#pragma unroll
        for (int i = 0; i < 8; i++) {
            float w = ws[i * Cin + c];
            acc[i][0] += w * fa.x; acc[i][1] += w * fa.y;
            acc[i][2] += w * fa.z; acc[i][3] += w * fa.w;
            acc[i][4] += w * fb.x; acc[i][5] += w * fb.y;
            acc[i][6] += w * fb.z; acc[i][7] += w * fb.w;
        }
        fa = na; fb = nb;
    }
#pragma unroll
    for (int j = 0; j < 8; j++) {
        float* op = OUT + (size_t)(cid + j) * Cout + o0;
        float4 v0 = make_float4(acc[0][j], acc[1][j], acc[2][j], acc[3][j]);
        float4 v1 = make_float4(acc[4][j], acc[5][j], acc[6][j], acc[7][j]);
        *(float4*)op = v0; *(float4*)(op + 4) = v1;
    }
}

// ---- cc skinny GEMM (single output set, software-pipelined, 256 threads) ----
__global__ __launch_bounds__(256)
void gemm_k(const float* __restrict__ Wparam,
            int ldw, int Cin, size_t bstride, int Cout) {
    extern __shared__ float ws[];
    const int R = 8;
    int o0 = blockIdx.y * R;
    for (int t = threadIdx.x; t < R * Cin; t += blockDim.x) {
        int i = t / Cin, c = t - i * Cin;
        ws[t] = Wparam[(o0 + i) * ldw + c];
    }
    __syncthreads();
    int cid = (blockIdx.x * blockDim.x + threadIdx.x) * 8;
    int b = cid / N3;
    int dn = cid - b * N3;
    const float* fin = g_cat + (size_t)b * bstride + dn;
    float acc[8][8];
#pragma unroll
    for (int i = 0; i < 8; i++)
#pragma unroll
        for (int j = 0; j < 8; j++) acc[i][j] = 0.f;
    float4 fa = *reinterpret_cast<const float4*>(fin);
    float4 fb = *reinterpret_cast<const float4*>(fin + 4);
#pragma unroll 2
    for (int c = 0; c < Cin; c++) {
        float4 na, nb;
        if (c + 1 < Cin) {
            const float* np = fin + (size_t)(c + 1) * N3;
            na = *reinterpret_cast<const float4*>(np);
            nb = *reinterpret_cast<const float4*>(np + 4);
        }
#pragma unroll
        for (int i = 0; i < 8; i++) {
            float w = ws[i * Cin + c];
            acc[i][0] += w * fa.x; acc[i][1] += w * fa.y;
            acc[i][2] += w * fa.z; acc[i][3] += w * fa.w;
            acc[i][4] += w * fb.x; acc[i][5] += w * fb.y;
            acc[i][6] += w * fb.z; acc[i][7] += w * fb.w;
        }
        fa = na; fb = nb;
    }
#pragma unroll
    for (int j = 0; j < 8; j++) {
        float* op = g_U + (size_t)(cid + j) * Cout + o0;
        float4 v0 = make_float4(acc[0][j], acc[1][j], acc[2][j], acc[3][j]);
        float4 v1 = make_float4(acc[4][j], acc[5][j], acc[6][j], acc[7][j]);
        *(float4*)op = v0; *(float4*)(op + 4) = v1;
    }
}

// ---- edge: gather + vec_act + mean over K (P points per block, 256 threads) ----
__global__ void edge_k(int Cout, int coff, int P) {
    int tid = threadIdx.x;
    int p = tid / Cout;
    int c = tid - p * Cout;
    int bn = blockIdx.x * P + p;
    int b = bn >> 10, n = bn & (NN - 1);
    const int* ip = g_idx + bn * KNNK;
    int bn0 = b * N3 + n;
    size_t sN = (size_t)NN * Cout;
    size_t pn = (size_t)bn0 * Cout + c;
    float bm0 = g_Bm[pn], bm1 = g_Bm[pn + sN], bm2 = g_Bm[pn + 2*sN];
    float bd0 = g_Bd[pn], bd1 = g_Bd[pn + sN], bd2 = g_Bd[pn + 2*sN];
    float a0 = 0.f, a1 = 0.f, a2 = 0.f;
    for (int k = 0; k < KNNK; k++) {
        int j = ip[k];
        size_t pj = (size_t)(b * N3 + j) * Cout + c;
        float y0 = g_A[pj]        + bm0;
        float y1 = g_A[pj + sN]   + bm1;
        float y2 = g_A[pj + 2*sN] + bm2;
        float d0 = g_Ad[pj]        + bd0;
        float d1 = g_Ad[pj + sN]   + bd1;
        float d2 = g_Ad[pj + 2*sN] + bd2;
        float dm = fmaxf(sqrtf(d0*d0 + d1*d1 + d2*d2), EPSF);
        float k0 = d0/dm, k1 = d1/dm, k2 = d2/dm;
        float dot = y0*k0 + y1*k1 + y2*k2;
        float coef = (dot < 0.f) ? (-0.8f * dot) : 0.f;
        a0 += y0 + coef*k0; a1 += y1 + coef*k1; a2 += y2 + coef*k2;
    }
    const float s = 1.0f / 16.0f;
    size_t ob = ((size_t)(b * CATC + coff + c) * 3) * NN + n;
    g_cat[ob] = a0 * s; g_cat[ob + NN] = a1 * s; g_cat[ob + 2*NN] = a2 * s;
}

// ---- fused cc direction-dot + vec_act: one block per (b,n) ----
__global__ void ccfused_k(const float* __restrict__ ccD) {
    __shared__ float sk[3];
    int bn = blockIdx.x;
    int b = bn >> 10, n = bn & (NN - 1);
    int tid = threadIdx.x;
    int w = tid >> 5, lane = tid & 31;
    if (w < 3) {
        int cid = b * N3 + w * NN + n;
        const float* u = g_U + (size_t)cid * 128;
        float s = 0.f;
#pragma unroll
        for (int i = 0; i < 4; i++) s += ccD[i*32 + lane] * u[i*32 + lane];
        for (int off = 16; off > 0; off >>= 1)
            s += __shfl_down_sync(0xffffffffu, s, off);
        if (lane == 0) sk[w] = s;
    }
    __syncthreads();
    float d0 = sk[0], d1 = sk[1], d2 = sk[2];
    float dm = fmaxf(sqrtf(d0*d0 + d1*d1 + d2*d2), EPSF);
    float k0 = d0/dm, k1 = d1/dm, k2 = d2/dm;
    int bn0 = b * N3 + n;
    size_t sN = (size_t)NN * 128;
    size_t p = (size_t)bn0 * 128 + tid;
    float u0 = g_U[p], u1 = g_U[p + sN], u2 = g_U[p + 2*sN];
    float dot = u0*k0 + u1*k1 + u2*k2;
    float coef = (dot < 0.f) ? (-0.8f * dot) : 0.f;
    size_t ob = ((size_t)(b * 128 + tid) * 3) * NN + n;
    g_ycc[ob] = u0 + coef*k0; g_ycc[ob + NN] = u1 + coef*k1; g_ycc[ob + 2*NN] = u2 + coef*k2;
}

// ---- mean over N ----
__global__ void reduce_k() {
    __shared__ float s[256];
    const float* p = g_ycc + (size_t)blockIdx.x * NN;
    int t = threadIdx.x;
    s[t] = p[t] + p[t + 256] + p[t + 512] + p[t + 768];
    __syncthreads();
    for (int off = 128; off > 0; off >>= 1) {
        if (t < off) s[t] += s[t + off];
        __syncthreads();
    }
    if (t == 0) g_y[blockIdx.x] = s[0] * (1.0f / NN);
}

// ---- head helpers ----
__device__ __forceinline__ float bsum128(float v, float* s) {
    int t = threadIdx.x;
    s[t] = v; __syncthreads();
    for (int off = 64; off > 0; off >>= 1) {
        if (t < off) s[t] += s[t + off];
        __syncthreads();
    }
    float r = s[0]; __syncthreads();
    return r;
}
__device__ __forceinline__ void gemm3(float (*dst)[3], const float* W,
                                      const float (*src)[3], int Cout, int Cin, int c) {
    if (c < Cout) {
        float a0 = 0.f, a1 = 0.f, a2 = 0.f;
        for (int m = 0; m < Cin; m++) {
            float w = W[c * Cin + m];
            a0 += w * src[m][0]; a1 += w * src[m][1]; a2 += w * src[m][2];
        }
        dst[c][0] = a0; dst[c][1] = a1; dst[c][2] = a2;
    }
}
__device__ __forceinline__ void act_sq(float (*dst)[3], const float (*x)[3],
                                       const float* Wd, int C, int c) {
    if (c < C) {
        float d0 = 0.f, d1 = 0.f, d2 = 0.f;
        for (int m = 0; m < C; m++) {
            float w = Wd[c * C + m];
            d0 += w * x[m][0]; d1 += w * x[m][1]; d2 += w * x[m][2];
        }
        float dm = fmaxf(sqrtf(d0*d0 + d1*d1 + d2*d2), EPSF);
        float k0 = d0/dm, k1 = d1/dm, k2 = d2/dm;
        float dot = x[c][0]*k0 + x[c][1]*k1 + x[c][2]*k2;
        float coef = (dot < 0.f) ? (-0.8f * dot) : 0.f;
        dst[c][0] = x[c][0] + coef*k0;
        dst[c][1] = x[c][1] + coef*k1;
        dst[c][2] = x[c][2] + coef*k2;
    }
}

// ---- head: 2 blocks per batch ----
__global__ void head_k(const float* __restrict__ fcO,
                       const float* __restrict__ rbDin, const float* __restrict__ rbW0,
                       const float* __restrict__ rbDh,  const float* __restrict__ rbW1,
                       const float* __restrict__ rbWs,
                       const float* __restrict__ m0W, const float* __restrict__ m0D,
                       const float* __restrict__ m1W, const float* __restrict__ m1D,
                       const float* __restrict__ l0W, const float* __restrict__ l0D,
                       const float* __restrict__ l1W, const float* __restrict__ l1D,
                       const float* __restrict__ fimW, const float* __restrict__ filW,
                       float* __restrict__ out) {
    int b = blockIdx.x >> 1;
    int branch = blockIdx.x & 1;
    int c = threadIdx.x;
    __shared__ float sy[128][3], syn[128][3], t0[128][3], t1[128][3], t2[128][3];
    __shared__ float sred[128];
    __shared__ float sR[9];

    float y0 = g_y[(b*128 + c)*3 + 0];
    float y1 = g_y[(b*128 + c)*3 + 1];
    float y2 = g_y[(b*128 + c)*3 + 2];
    sy[c][0] = y0; sy[c][1] = y1; sy[c][2] = y2;
    float nc = sqrtf(y0*y0 + y1*y1 + y2*y2);
    __syncthreads();

    if (branch == 0) {
        float ss = bsum128(nc + EPSF, sred);
        if (c == 0) out[1060 + b] = ss * (1.0f / 128.0f) * 640.0f;
    }

    float S = bsum128(nc * nc, sred);
    float nn = nc / fmaxf(sqrtf(S), EPSF);
    float invn = fmaxf(nc, EPSF);
    syn[c][0] = y0/invn*nn; syn[c][1] = y1/invn*nn; syn[c][2] = y2/invn*nn;
    __syncthreads();

    if (branch == 0) {
        for (int o = 0; o < 3; o++) {
            float wo = fcO[o * 128 + c];
            for (int d = 0; d < 3; d++) {
                float r = bsum128(wo * syn[c][d], sred);
                if (c == 0) sR[d*3 + o] = r;
            }
        }
        __syncthreads();

        if (c == 0) {
            float X[9], Cf[9];
            float fn = 0.f;
            for (int i = 0; i < 9; i++) { X[i] = sR[i]; fn += X[i]*X[i]; }
            fn = sqrtf(fn); if (fn < 1e-20f) fn = 1e-20f;
            for (int i = 0; i < 9; i++) X[i] /= fn;
            for (int it = 0; it < 25; it++) {
                Cf[0] =  (X[4]*X[8] - X[5]*X[7]);
                Cf[1] = -(X[3]*X[8] - X[5]*X[6]);
                Cf[2] =  (X[3]*X[7] - X[4]*X[6]);
                Cf[3] = -(X[1]*X[8] - X[2]*X[7]);
                Cf[4] =  (X[0]*X[8] - X[2]*X[6]);
                Cf[5] = -(X[0]*X[7] - X[1]*X[6]);
                Cf[6] =  (X[1]*X[5] - X[2]*X[4]);
                Cf[7] = -(X[0]*X[5] - X[2]*X[3]);
                Cf[8] =  (X[0]*X[4] - X[1]*X[3]);
                float det = X[0]*Cf[0] + X[1]*Cf[1] + X[2]*Cf[2];
                float ad = fabsf(det);
                if (ad < 1e-30f) break;
                float z = 1.0f / cbrtf(ad);
                float invd = 1.0f / det;
                for (int i = 0; i < 9; i++)
                    X[i] = 0.5f * (z * X[i] + (Cf[i] * invd) / z);
            }
            for (int i = 0; i < 3; i++)
                for (int j = 0; j < 3; j++)
                    out[1024 + b*9 + i*3 + j] = X[j*3 + i];
        }

        act_sq(t0, sy, rbDin, 128, c);
        __syncthreads();
        gemm3(t1, rbW0, t0, 64, 128, c);
        __syncthreads();
        act_sq(t2, t1, rbDh, 64, c);
        __syncthreads();
        if (c < 3) {
            float dx = 0.f;
            for (int m = 0; m < 64; m++) dx += rbW1[m] * t2[m][c];
            float wsv = 0.f;
            for (int m = 0; m < 128; m++) wsv += rbWs[m] * sy[m][c];
            out[1064 + b*3 + c] = (wsv + dx) * 640.0f;
        }
        __syncthreads();

        gemm3(t0, m0W, syn, 128, 128, c); __syncthreads();
        act_sq(t1, t0, m0D, 128, c);      __syncthreads();
        gemm3(t0, m1W, t1, 128, 128, c);  __syncthreads();
        act_sq(t2, t0, m1D, 128, c);      __syncthreads();
        gemm3(t0, fimW, t2, 128, 128, c); __syncthreads();
        out[b*128 + c] = t2[c][0]*t0[c][0] + t2[c][1]*t0[c][1] + t2[c][2]*t0[c][2];
    } else {
        gemm3(t0, l0W, syn, 128, 128, c); __syncthreads();
        act_sq(t1, t0, l0D, 128, c);      __syncthreads();
        gemm3(t0, l1W, t1, 128, 128, c);  __syncthreads();
        act_sq(t2, t0, l1D, 128, c);      __syncthreads();
        gemm3(t0, filW, t2, 128, 128, c); __syncthreads();
        out[512 + b*128 + c] = t2[c][0]*t0[c][0] + t2[c][1]*t0[c][1] + t2[c][2]*t0[c][2];
    }
}

// ---- host-side layer driver: 2 launches per layer ----
static void run_layer(const float* W, int layer, int Cin, int Cout,
                      const float* xin, int finoff, size_t bstride, int coff) {
    int wcols = 2 * Cin;
    int wpoff = layer * WPSLOT;
    dim3 g(6, 4 * (Cout / 8));
    size_t sm = (size_t)8 * Cin * sizeof(float);
    gemm4_k<<<g, 256, sm>>>(W, wpoff, wcols, xin, finoff, Cin, bstride, Cout);
    int P = 256 / Cout;
    edge_k<<<BB * NN / P, 256>>>(Cout, coff, P);
}

extern "C" void kernel_launch(void* const* d_in, const int* in_sizes, int n_in,
                              void* d_out, int out_size) {
    const float* x    = (const float*)d_in[0];
    const float* c1W  = (const float*)d_in[2];
    const float* c1D  = (const float*)d_in[3];
    const float* c2W  = (const float*)d_in[4];
    const float* c2D  = (const float*)d_in[5];
    const float* c3W  = (const float*)d_in[6];
    const float* c3D  = (const float*)d_in[7];
    const float* c4W  = (const float*)d_in[8];
    const float* c4D  = (const float*)d_in[9];
    const float* ccW  = (const float*)d_in[10];
    const float* ccD  = (const float*)d_in[11];
    const float* fcO  = (const float*)d_in[12];
    const float* m0W  = (const float*)d_in[13];
    const float* m0D  = (const float*)d_in[14];
    const float* m1W  = (const float*)d_in[15];
    const float* m1D  = (const float*)d_in[16];
    const float* l0W  = (const float*)d_in[17];
    const float* l0D  = (const float*)d_in[18];
    const float* l1W  = (const float*)d_in[19];
    const float* l1D  = (const float*)d_in[20];
    const float* fimW = (const float*)d_in[21];
    const float* filW = (const float*)d_in[22];
    const float* rbDin= (const float*)d_in[23];
    const float* rbW0 = (const float*)d_in[24];
    const float* rbDh = (const float*)d_in[25];
    const float* rbW1 = (const float*)d_in[26];
    const float* rbWs = (const float*)d_in[27];
    float* out = (float*)d_out;

    pre_k<<<BB * NN + 352, 256>>>(x, c1W, c1D, c2W, c2D, c3W, c3D, c4W, c4D);

    size_t catbs = (size_t)CATC * N3;
    run_layer(c1W, 0, 1,   32,  x,       0,        (size_t)N3, 0);
    run_layer(c2W, 1, 32,  64,  nullptr, 0,        catbs,      32);
    run_layer(c3W, 2, 64,  128, nullptr, 32 * N3,  catbs,      96);
    run_layer(c4W, 3, 128, 128, nullptr, 96 * N3,  catbs,      224);

    // cc layer
    {
        dim3 g(6, 16);
        size_t sm = (size_t)8 * CATC * sizeof(float);
        gemm_k<<<g, 256, sm>>>(ccW, CATC, CATC, catbs, 128);
    }
    ccfused_k<<<BB * NN, 128>>>(ccD);
    reduce_k<<<BB * 128 * 3, 256>>>();

    head_k<<<BB * 2, 128>>>(fcO, rbDin, rbW0, rbDh, rbW1, rbWs,
                            m0W, m0D, m1W, m1D, l0W, l0D, l1W, l1D,
                            fimW, filW, out);
}

// round 14
// speedup vs baseline: 1.4740x; 1.0031x over previous
#include <cuda_runtime.h>
#include <math.h>

#define BB 4
#define NN 1024
#define KNNK 16
#define N3 3072
#define NCOL 12288
#define CATC 352
#define WPSLOT 32768
#define EPSF 1e-12f

// ---- static scratch ----
__device__ __align__(16) float g_cat[BB * CATC * 3 * NN];  // [b][c][d][n]
__device__ __align__(16) float g_A [NCOL * 128];           // [cid][o], cid=b*3N+d*N+n
__device__ __align__(16) float g_Bm[NCOL * 128];
__device__ __align__(16) float g_Ad[NCOL * 128];
__device__ __align__(16) float g_Bd[NCOL * 128];
__device__ __align__(16) float g_U [NCOL * 128];
__device__ __align__(16) float g_Wp[4 * WPSLOT];
__device__ __align__(16) float g_ycc[BB * 128 * 3 * NN];
__device__ __align__(16) float g_y[BB * 128 * 3];
__device__ int g_idx[BB * NN * KNNK];

// ---- fused KNN + weight-combine: one launch ----
// blocks [0, 4096): KNN (PROTECTED d2 rounding structure — do not change)
// blocks [4096, 4448): Wp = Wd @ W for all 4 layers
__global__ void pre_k(const float* __restrict__ x,
                      const float* __restrict__ W1, const float* __restrict__ D1,
                      const float* __restrict__ W2, const float* __restrict__ D2,
                      const float* __restrict__ W3, const float* __restrict__ D3,
                      const float* __restrict__ W4, const float* __restrict__ D4) {
    __shared__ float ssq[NN];
    __shared__ float sd[NN];
    __shared__ float rv[8];
    __shared__ int   ri[8];
    if (blockIdx.x >= BB * NN) {
        int bid = blockIdx.x - BB * NN;
        const float *W, *Wd; int Cin, Cout, o, slot;
        if (bid < 32)       { W = W1; Wd = D1; Cin = 1;   Cout = 32;  o = bid;       slot = 0; }
        else if (bid < 96)  { W = W2; Wd = D2; Cin = 32;  Cout = 64;  o = bid - 32;  slot = 1; }
        else if (bid < 224) { W = W3; Wd = D3; Cin = 64;  Cout = 128; o = bid - 96;  slot = 2; }
        else                { W = W4; Wd = D4; Cin = 128; Cout = 128; o = bid - 224; slot = 3; }
        int wcols = 2 * Cin;
        int j = threadIdx.x;
        if (j >= wcols) return;
        float s = 0.f;
        for (int m = 0; m < Cout; m++) s += Wd[o * Cout + m] * W[m * wcols + j];
        g_Wp[slot * WPSLOT + o * wcols + j] = s;
        return;
    }
    int bn = blockIdx.x;
    int b = bn >> 10, n = bn & (NN - 1);
    int tid = threadIdx.x;
    const float* xb = x + (size_t)b * N3;
    for (int m = tid; m < NN; m += 256) {
        float qx = xb[m], qy = xb[NN + m], qz = xb[2*NN + m];
        ssq[m] = __fadd_rn(__fadd_rn(__fmul_rn(qx, qx), __fmul_rn(qy, qy)),
                           __fmul_rn(qz, qz));
    }
    __syncthreads();
    float px = xb[n], py = xb[NN + n], pz = xb[2*NN + n];
    float sqn = ssq[n];
    for (int m = tid; m < NN; m += 256) {
        float qx = xb[m], qy = xb[NN + m], qz = xb[2*NN + m];
        float dot = __fmaf_rn(pz, qz, __fmaf_rn(py, qy, __fmul_rn(px, qx)));
        sd[m] = __fsub_rn(__fadd_rn(sqn, ssq[m]), __fmul_rn(2.0f, dot));
    }
    __syncthreads();
    for (int k = 0; k < KNNK; k++) {
        float bv = INFINITY; int bi = 0x7fffffff;
        for (int m = tid; m < NN; m += 256) {
            float v = sd[m];
            if (v < bv || (v == bv && m < bi)) { bv = v; bi = m; }
        }
        for (int off = 16; off > 0; off >>= 1) {
            float ov = __shfl_down_sync(0xffffffffu, bv, off);
            int   oi = __shfl_down_sync(0xffffffffu, bi, off);
            if (ov < bv || (ov == bv && oi < bi)) { bv = ov; bi = oi; }
        }
        if ((tid & 31) == 0) { rv[tid >> 5] = bv; ri[tid >> 5] = bi; }
        __syncthreads();
        // stage 2: lexicographic (v, i) min over 8 warp results via warp 0 shuffle
        // (associative total order -> identical winner to sequential scan)
        if (tid < 32) {
            float fv = (tid < 8) ? rv[tid] : INFINITY;
            int   fi = (tid < 8) ? ri[tid] : 0x7fffffff;
            for (int off = 4; off > 0; off >>= 1) {
                float ov = __shfl_down_sync(0xffffffffu, fv, off);
                int   oi = __shfl_down_sync(0xffffffffu, fi, off);
                if (ov < fv || (ov == fv && oi < fi)) { fv = ov; fi = oi; }
            }
            if (tid == 0) {
                g_idx[bn * KNNK + k] = fi;
                sd[fi] = INFINITY;
            }
        }
        __syncthreads();
    }
}

// ---- output selector ----
__device__ __forceinline__ float* out_sel(int s) {
    switch (s) {
        case 0: return g_A;
        case 1: return g_Bm;
        case 2: return g_Ad;
        default: return g_Bd;
    }
}

// ---- fused 4-way skinny GEMM: software-pipelined, 256 threads (unchanged) ----
__global__ __launch_bounds__(256)
void gemm4_k(const float* __restrict__ Wparam, int wpoff, int ldw,
             const float* __restrict__ xin, int finoff,
             int Cin, size_t bstride, int Cout) {
    extern __shared__ float ws[];
    const int R = 8;
    int groups = Cout >> 3;
    int which = blockIdx.y / groups;          // 0..3
    int o0 = (blockIdx.y - which * groups) * R;
    int mode = which & 1;
    const float* W = (which & 2) ? (g_Wp + wpoff) : Wparam;
    float* OUT = out_sel(which);
    for (int t = threadIdx.x; t < R * Cin; t += blockDim.x) {
        int i = t / Cin, c = t - i * Cin;
        float w = W[(o0 + i) * ldw + c];
        if (mode) w = W[(o0 + i) * ldw + Cin + c] - w;
        ws[t] = w;
    }
    __syncthreads();
    const float* FIN = xin ? xin : (g_cat + finoff);
    int cid = (blockIdx.x * blockDim.x + threadIdx.x) * 8;
    int b = cid / N3;
    int dn = cid - b * N3;
    const float* fin = FIN + (size_t)b * bstride + dn;
    float acc[8][8];
#pragma unroll
    for (int i = 0; i < 8; i++)
#pragma unroll
        for (int j = 0; j < 8; j++) acc[i][j] = 0.f;
    float4 fa = *reinterpret_cast<const float4*>(fin);
    float4 fb = *reinterpret_cast<const float4*>(fin + 4);
#pragma unroll 2
    for (int c = 0; c < Cin; c++) {
        float4 na, nb;
        if (c + 1 < Cin) {
            const float* np = fin + (size_t)(c + 1) * N3;
            na = *reinterpret_cast<const float4*>(np);
            nb = *reinterpret_cast<const float4*>(np + 4);
        }
#pragma unroll
        for (int i = 0; i < 8; i++) {
            float w = ws[i * Cin + c];
            acc[i][0] += w * fa.x; acc[i][1] += w * fa.y;
            acc[i][2] += w * fa.z; acc[i][3] += w * fa.w;
            acc[i][4] += w * fb.x; acc[i][5] += w * fb.y;
            acc[i][6] += w * fb.z; acc[i][7] += w * fb.w;
        }
        fa = na; fb = nb;
    }
#pragma unroll
    for (int j = 0; j < 8; j++) {
        float* op = OUT + (size_t)(cid + j) * Cout + o0;
        float4 v0 = make_float4(acc[0][j], acc[1][j], acc[2][j], acc[3][j]);
        float4 v1 = make_float4(acc[4][j], acc[5][j], acc[6][j], acc[7][j]);
        *(float4*)op = v0; *(float4*)(op + 4) = v1;
    }
}

// ---- cc skinny GEMM (unchanged) ----
__global__ __launch_bounds__(256)
void gemm_k(const float* __restrict__ Wparam,
            int ldw, int Cin, size_t bstride, int Cout) {
    extern __shared__ float ws[];
    const int R = 8;
    int o0 = blockIdx.y * R;
    for (int t = threadIdx.x; t < R * Cin; t += blockDim.x) {
        int i = t / Cin, c = t - i * Cin;
        ws[t] = Wparam[(o0 + i) * ldw + c];
    }
    __syncthreads();
    int cid = (blockIdx.x * blockDim.x + threadIdx.x) * 8;
    int b = cid / N3;
    int dn = cid - b * N3;
    const float* fin = g_cat + (size_t)b * bstride + dn;
    float acc[8][8];
#pragma unroll
    for (int i = 0; i < 8; i++)
#pragma unroll
        for (int j = 0; j < 8; j++) acc[i][j] = 0.f;
    float4 fa = *reinterpret_cast<const float4*>(fin);
    float4 fb = *reinterpret_cast<const float4*>(fin + 4);
#pragma unroll 2
    for (int c = 0; c < Cin; c++) {
        float4 na, nb;
        if (c + 1 < Cin) {
            const float* np = fin + (size_t)(c + 1) * N3;
            na = *reinterpret_cast<const float4*>(np);
            nb = *reinterpret_cast<const float4*>(np + 4);
        }
#pragma unroll
        for (int i = 0; i < 8; i++) {
            float w = ws[i * Cin + c];
            acc[i][0] += w * fa.x; acc[i][1] += w * fa.y;
            acc[i][2] += w * fa.z; acc[i][3] += w * fa.w;
            acc[i][4] += w * fb.x; acc[i][5] += w * fb.y;
            acc[i][6] += w * fb.z; acc[i][7] += w * fb.w;
        }
        fa = na; fb = nb;
    }
#pragma unroll
    for (int j = 0; j < 8; j++) {
        float* op = g_U + (size_t)(cid + j) * Cout + o0;
        float4 v0 = make_float4(acc[0][j], acc[1][j], acc[2][j], acc[3][j]);
        float4 v1 = make_float4(acc[4][j], acc[5][j], acc[6][j], acc[7][j]);
        *(float4*)op = v0; *(float4*)(op + 4) = v1;
    }
}

// ---- edge: float2-vectorized gather + vec_act + mean over K ----
// threads: P * (Cout/2); each thread handles 2 adjacent channels
__global__ void edge_k(int Cout, int coff, int P) {
    int half = Cout >> 1;
    int tid = threadIdx.x;
    int p = tid / half;
    int c2 = tid - p * half;          // channels 2*c2, 2*c2+1
    int bn = blockIdx.x * P + p;
    int b = bn >> 10, n = bn & (NN - 1);
    const int* ip = g_idx + bn * KNNK;
    int bn0 = b * N3 + n;
    size_t sN = (size_t)NN * Cout;
    size_t pn = (size_t)bn0 * Cout + 2 * c2;
    float2 bm0 = *(const float2*)&g_Bm[pn];
    float2 bm1 = *(const float2*)&g_Bm[pn + sN];
    float2 bm2 = *(const float2*)&g_Bm[pn + 2*sN];
    float2 bd0 = *(const float2*)&g_Bd[pn];
    float2 bd1 = *(const float2*)&g_Bd[pn + sN];
    float2 bd2 = *(const float2*)&g_Bd[pn + 2*sN];
    float ax0 = 0.f, ax1 = 0.f, ax2 = 0.f;
    float bx0 = 0.f, bx1 = 0.f, bx2 = 0.f;
    for (int k = 0; k < KNNK; k++) {
        int j = ip[k];
        size_t pj = (size_t)(b * N3 + j) * Cout + 2 * c2;
        float2 A0 = *(const float2*)&g_A[pj];
        float2 A1 = *(const float2*)&g_A[pj + sN];
        float2 A2 = *(const float2*)&g_A[pj + 2*sN];
        float2 D0 = *(const float2*)&g_Ad[pj];
        float2 D1 = *(const float2*)&g_Ad[pj + sN];
        float2 D2 = *(const float2*)&g_Ad[pj + 2*sN];
        // channel 2*c2
        {
            float y0 = A0.x + bm0.x, y1 = A1.x + bm1.x, y2 = A2.x + bm2.x;
            float d0 = D0.x + bd0.x, d1 = D1.x + bd1.x, d2 = D2.x + bd2.x;
            float dm = fmaxf(sqrtf(d0*d0 + d1*d1 + d2*d2), EPSF);
            float k0 = d0/dm, k1 = d1/dm, k2 = d2/dm;
            float dot = y0*k0 + y1*k1 + y2*k2;
            float coef = (dot < 0.f) ? (-0.8f * dot) : 0.f;
            ax0 += y0 + coef*k0; ax1 += y1 + coef*k1; ax2 += y2 + coef*k2;
        }
        // channel 2*c2+1
        {
            float y0 = A0.y + bm0.y, y1 = A1.y + bm1.y, y2 = A2.y + bm2.y;
            float d0 = D0.y + bd0.y, d1 = D1.y + bd1.y, d2 = D2.y + bd2.y;
            float dm = fmaxf(sqrtf(d0*d0 + d1*d1 + d2*d2), EPSF);
            float k0 = d0/dm, k1 = d1/dm, k2 = d2/dm;
            float dot = y0*k0 + y1*k1 + y2*k2;
            float coef = (dot < 0.f) ? (-0.8f * dot) : 0.f;
            bx0 += y0 + coef*k0; bx1 += y1 + coef*k1; bx2 += y2 + coef*k2;
        }
    }
    const float s = 1.0f / 16.0f;
    int ch = 2 * c2;
    size_t ob = ((size_t)(b * CATC + coff + ch) * 3) * NN + n;
    g_cat[ob] = ax0 * s; g_cat[ob + NN] = ax1 * s; g_cat[ob + 2*NN] = ax2 * s;
    size_t ob2 = ob + (size_t)3 * NN;
    g_cat[ob2] = bx0 * s; g_cat[ob2 + NN] = bx1 * s; g_cat[ob2 + 2*NN] = bx2 * s;
}

// ---- fused cc direction-dot + vec_act ----
__global__ void ccfused_k(const float* __restrict__ ccD) {
    __shared__ float sk[3];
    int bn = blockIdx.x;
    int b = bn >> 10, n = bn & (NN - 1);
    int tid = threadIdx.x;
    int w = tid >> 5, lane = tid & 31;
    if (w < 3) {
        int cid = b * N3 + w * NN + n;
        const float* u = g_U + (size_t)cid * 128;
        float s = 0.f;
#pragma unroll
        for (int i = 0; i < 4; i++) s += ccD[i*32 + lane] * u[i*32 + lane];
        for (int off = 16; off > 0; off >>= 1)
            s += __shfl_down_sync(0xffffffffu, s, off);
        if (lane == 0) sk[w] = s;
    }
    __syncthreads();
    float d0 = sk[0], d1 = sk[1], d2 = sk[2];
    float dm = fmaxf(sqrtf(d0*d0 + d1*d1 + d2*d2), EPSF);
    float k0 = d0/dm, k1 = d1/dm, k2 = d2/dm;
    int bn0 = b * N3 + n;
    size_t sN = (size_t)NN * 128;
    size_t p = (size_t)bn0 * 128 + tid;
    float u0 = g_U[p], u1 = g_U[p + sN], u2 = g_U[p + 2*sN];
    float dot = u0*k0 + u1*k1 + u2*k2;
    float coef = (dot < 0.f) ? (-0.8f * dot) : 0.f;
    size_t ob = ((size_t)(b * 128 + tid) * 3) * NN + n;
    g_ycc[ob] = u0 + coef*k0; g_ycc[ob + NN] = u1 + coef*k1; g_ycc[ob + 2*NN] = u2 + coef*k2;
}

// ---- mean over N ----
__global__ void reduce_k() {
    __shared__ float s[256];
    const float* p = g_ycc + (size_t)blockIdx.x * NN;
    int t = threadIdx.x;
    s[t] = p[t] + p[t + 256] + p[t + 512] + p[t + 768];
    __syncthreads();
    for (int off = 128; off > 0; off >>= 1) {
        if (t < off) s[t] += s[t + off];
        __syncthreads();
    }
    if (t == 0) g_y[blockIdx.x] = s[0] * (1.0f / NN);
}

// ---- head helpers ----
__device__ __forceinline__ float bsum128(float v, float* s) {
    int t = threadIdx.x;
    s[t] = v; __syncthreads();
    for (int off = 64; off > 0; off >>= 1) {
        if (t < off) s[t] += s[t + off];
        __syncthreads();
    }
    float r = s[0]; __syncthreads();
    return r;
}
__device__ __forceinline__ void gemm3(float (*dst)[3], const float* W,
                                      const float (*src)[3], int Cout, int Cin, int c) {
    if (c < Cout) {
        float a0 = 0.f, a1 = 0.f, a2 = 0.f;
        for (int m = 0; m < Cin; m++) {
            float w = W[c * Cin + m];
            a0 += w * src[m][0]; a1 += w * src[m][1]; a2 += w * src[m][2];
        }
        dst[c][0] = a0; dst[c][1] = a1; dst[c][2] = a2;
    }
}
__device__ __forceinline__ void act_sq(float (*dst)[3], const float (*x)[3],
                                       const float* Wd, int C, int c) {
    if (c < C) {
        float d0 = 0.f, d1 = 0.f, d2 = 0.f;
        for (int m = 0; m < C; m++) {
            float w = Wd[c * C + m];
            d0 += w * x[m][0]; d1 += w * x[m][1]; d2 += w * x[m][2];
        }
        float dm = fmaxf(sqrtf(d0*d0 + d1*d1 + d2*d2), EPSF);
        float k0 = d0/dm, k1 = d1/dm, k2 = d2/dm;
        float dot = x[c][0]*k0 + x[c][1]*k1 + x[c][2]*k2;
        float coef = (dot < 0.f) ? (-0.8f * dot) : 0.f;
        dst[c][0] = x[c][0] + coef*k0;
        dst[c][1] = x[c][1] + coef*k1;
        dst[c][2] = x[c][2] + coef*k2;
    }
}

// ---- head: 2 blocks per batch ----
__global__ void head_k(const float* __restrict__ fcO,
                       const float* __restrict__ rbDin, const float* __restrict__ rbW0,
                       const float* __restrict__ rbDh,  const float* __restrict__ rbW1,
                       const float* __restrict__ rbWs,
                       const float* __restrict__ m0W, const float* __restrict__ m0D,
                       const float* __restrict__ m1W, const float* __restrict__ m1D,
                       const float* __restrict__ l0W, const float* __restrict__ l0D,
                       const float* __restrict__ l1W, const float* __restrict__ l1D,
                       const float* __restrict__ fimW, const float* __restrict__ filW,
                       float* __restrict__ out) {
    int b = blockIdx.x >> 1;
    int branch = blockIdx.x & 1;
    int c = threadIdx.x;
    __shared__ float sy[128][3], syn[128][3], t0[128][3], t1[128][3], t2[128][3];
    __shared__ float sred[128];
    __shared__ float sR[9];

    float y0 = g_y[(b*128 + c)*3 + 0];
    float y1 = g_y[(b*128 + c)*3 + 1];
    float y2 = g_y[(b*128 + c)*3 + 2];
    sy[c][0] = y0; sy[c][1] = y1; sy[c][2] = y2;
    float nc = sqrtf(y0*y0 + y1*y1 + y2*y2);
    __syncthreads();

    if (branch == 0) {
        float ss = bsum128(nc + EPSF, sred);
        if (c == 0) out[1060 + b] = ss * (1.0f / 128.0f) * 640.0f;
    }

    float S = bsum128(nc * nc, sred);
    float nn = nc / fmaxf(sqrtf(S), EPSF);
    float invn = fmaxf(nc, EPSF);
    syn[c][0] = y0/invn*nn; syn[c][1] = y1/invn*nn; syn[c][2] = y2/invn*nn;
    __syncthreads();

    if (branch == 0) {
        for (int o = 0; o < 3; o++) {
            float wo = fcO[o * 128 + c];
            for (int d = 0; d < 3; d++) {
                float r = bsum128(wo * syn[c][d], sred);
                if (c == 0) sR[d*3 + o] = r;
            }
        }
        __syncthreads();

        if (c == 0) {
            float X[9], Cf[9];
            float fn = 0.f;
            for (int i = 0; i < 9; i++) { X[i] = sR[i]; fn += X[i]*X[i]; }
            fn = sqrtf(fn); if (fn < 1e-20f) fn = 1e-20f;
            for (int i = 0; i < 9; i++) X[i] /= fn;
            for (int it = 0; it < 25; it++) {
                Cf[0] =  (X[4]*X[8] - X[5]*X[7]);
                Cf[1] = -(X[3]*X[8] - X[5]*X[6]);
                Cf[2] =  (X[3]*X[7] - X[4]*X[6]);
                Cf[3] = -(X[1]*X[8] - X[2]*X[7]);
                Cf[4] =  (X[0]*X[8] - X[2]*X[6]);
                Cf[5] = -(X[0]*X[7] - X[1]*X[6]);
                Cf[6] =  (X[1]*X[5] - X[2]*X[4]);
                Cf[7] = -(X[0]*X[5] - X[2]*X[3]);
                Cf[8] =  (X[0]*X[4] - X[1]*X[3]);
                float det = X[0]*Cf[0] + X[1]*Cf[1] + X[2]*Cf[2];
                float ad = fabsf(det);
                if (ad < 1e-30f) break;
                float z = 1.0f / cbrtf(ad);
                float invd = 1.0f / det;
                for (int i = 0; i < 9; i++)
                    X[i] = 0.5f * (z * X[i] + (Cf[i] * invd) / z);
            }
            for (int i = 0; i < 3; i++)
                for (int j = 0; j < 3; j++)
                    out[1024 + b*9 + i*3 + j] = X[j*3 + i];
        }

        act_sq(t0, sy, rbDin, 128, c);
        __syncthreads();
        gemm3(t1, rbW0, t0, 64, 128, c);
        __syncthreads();
        act_sq(t2, t1, rbDh, 64, c);
        __syncthreads();
        if (c < 3) {
            float dx = 0.f;
            for (int m = 0; m < 64; m++) dx += rbW1[m] * t2[m][c];
            float wsv = 0.f;
            for (int m = 0; m < 128; m++) wsv += rbWs[m] * sy[m][c];
            out[1064 + b*3 + c] = (wsv + dx) * 640.0f;
        }
        __syncthreads();

        gemm3(t0, m0W, syn, 128, 128, c); __syncthreads();
        act_sq(t1, t0, m0D, 128, c);      __syncthreads();
        gemm3(t0, m1W, t1, 128, 128, c);  __syncthreads();
        act_sq(t2, t0, m1D, 128, c);      __syncthreads();
        gemm3(t0, fimW, t2, 128, 128, c); __syncthreads();
        out[b*128 + c] = t2[c][0]*t0[c][0] + t2[c][1]*t0[c][1] + t2[c][2]*t0[c][2];
    } else {
        gemm3(t0, l0W, syn, 128, 128, c); __syncthreads();
        act_sq(t1, t0, l0D, 128, c);      __syncthreads();
        gemm3(t0, l1W, t1, 128, 128, c);  __syncthreads();
        act_sq(t2, t0, l1D, 128, c);      __syncthreads();
        gemm3(t0, filW, t2, 128, 128, c); __syncthreads();
        out[512 + b*128 + c] = t2[c][0]*t0[c][0] + t2[c][1]*t0[c][1] + t2[c][2]*t0[c][2];
    }
}

// ---- host-side layer driver: 2 launches per layer ----
static void run_layer(const float* W, int layer, int Cin, int Cout,
                      const float* xin, int finoff, size_t bstride, int coff) {
    int wcols = 2 * Cin;
    int wpoff = layer * WPSLOT;
    dim3 g(6, 4 * (Cout / 8));
    size_t sm = (size_t)8 * Cin * sizeof(float);
    gemm4_k<<<g, 256, sm>>>(W, wpoff, wcols, xin, finoff, Cin, bstride, Cout);
    int P = 256 / (Cout / 2);
    edge_k<<<BB * NN / P, 256>>>(Cout, coff, P);
}

extern "C" void kernel_launch(void* const* d_in, const int* in_sizes, int n_in,
                              void* d_out, int out_size) {
    const float* x    = (const float*)d_in[0];
    const float* c1W  = (const float*)d_in[2];
    const float* c1D  = (const float*)d_in[3];
    const float* c2W  = (const float*)d_in[4];
    const float* c2D  = (const float*)d_in[5];
    const float* c3W  = (const float*)d_in[6];
    const float* c3D  = (const float*)d_in[7];
    const float* c4W  = (const float*)d_in[8];
    const float* c4D  = (const float*)d_in[9];
    const float* ccW  = (const float*)d_in[10];
    const float* ccD  = (const float*)d_in[11];
    const float* fcO  = (const float*)d_in[12];
    const float* m0W  = (const float*)d_in[13];
    const float* m0D  = (const float*)d_in[14];
    const float* m1W  = (const float*)d_in[15];
    const float* m1D  = (const float*)d_in[16];
    const float* l0W  = (const float*)d_in[17];
    const float* l0D  = (const float*)d_in[18];
    const float* l1W  = (const float*)d_in[19];
    const float* l1D  = (const float*)d_in[20];
    const float* fimW = (const float*)d_in[21];
    const float* filW = (const float*)d_in[22];
    const float* rbDin= (const float*)d_in[23];
    const float* rbW0 = (const float*)d_in[24];
    const float* rbDh = (const float*)d_in[25];
    const float* rbW1 = (const float*)d_in[26];
    const float* rbWs = (const float*)d_in[27];
    float* out = (float*)d_out;

    pre_k<<<BB * NN + 352, 256>>>(x, c1W, c1D, c2W, c2D, c3W, c3D, c4W, c4D);

    size_t catbs = (size_t)CATC * N3;
    run_layer(c1W, 0, 1,   32,  x,       0,        (size_t)N3, 0);
    run_layer(c2W, 1, 32,  64,  nullptr, 0,        catbs,      32);
    run_layer(c3W, 2, 64,  128, nullptr, 32 * N3,  catbs,      96);
    run_layer(c4W, 3, 128, 128, nullptr, 96 * N3,  catbs,      224);

    // cc layer
    {
        dim3 g(6, 16);
        size_t sm = (size_t)8 * CATC * sizeof(float);
        gemm_k<<<g, 256, sm>>>(ccW, CATC, CATC, catbs, 128);
    }
    ccfused_k<<<BB * NN, 128>>>(ccD);
    reduce_k<<<BB * 128 * 3, 256>>>();

    head_k<<<BB * 2, 128>>>(fcO, rbDin, rbW0, rbDh, rbW1, rbWs,
                            m0W, m0D, m1W, m1D, l0W, l0D, l1W, l1D,
                            fimW, filW, out);
}